// round 1
// baseline (speedup 1.0000x reference)
#include <cuda_runtime.h>
#include <math.h>

// Problem constants
#define BB 4
#define NN 16384
#define CC 128
#define MM 1024
#define KK 32
#define PP (BB*MM*KK)     // 131072 points total
#define C1 131
#define O1 128
#define O2 128
#define O3 256
#define RAD2 0.16f
#define EPSV 1e-5f

// Scratch (static device globals; no allocation at runtime)
__device__ float  g_featT[(size_t)BB*NN*CC];     // (B,N,C)  33.5 MB
__device__ float  g_newxyz[BB*MM*3];
__device__ int    g_idx[BB*MM*KK];
__device__ float  g_y1[(size_t)O1*PP];           // 67 MB  channel-major (O,P)
__device__ float  g_y2[(size_t)O2*PP];           // 67 MB
__device__ float  g_y3[(size_t)O3*PP];           // 134 MB
__device__ float2 g_ab1[O1];
__device__ float2 g_ab2[O2];
__device__ float2 g_ab3[O3];

// ---------------------------------------------------------------------------
// K0: gather new_xyz; also write to output region [0, B*M*3)
// ---------------------------------------------------------------------------
__global__ void k_gather_newxyz(const float* __restrict__ xyz,
                                const int* __restrict__ indices,
                                float* __restrict__ out) {
    int i = blockIdx.x * blockDim.x + threadIdx.x;  // over B*M
    if (i >= BB * MM) return;
    int b = i / MM;
    int n = indices[i];
    const float* src = xyz + ((size_t)b * NN + n) * 3;
    float x = src[0], y = src[1], z = src[2];
    g_newxyz[i*3+0] = x; g_newxyz[i*3+1] = y; g_newxyz[i*3+2] = z;
    out[i*3+0] = x; out[i*3+1] = y; out[i*3+2] = z;
}

// ---------------------------------------------------------------------------
// K1: transpose features (B,C,N) -> (B,N,C) so point-gathers are contiguous
// ---------------------------------------------------------------------------
__global__ void k_transpose_feat(const float* __restrict__ f) {
    __shared__ float t[32][33];
    int b  = blockIdx.z;
    int c0 = blockIdx.y * 32;
    int n0 = blockIdx.x * 32;
    int tx = threadIdx.x, ty = threadIdx.y;  // 32 x 8
    #pragma unroll
    for (int j = 0; j < 32; j += 8)
        t[ty + j][tx] = f[((size_t)b * CC + c0 + ty + j) * NN + n0 + tx];
    __syncthreads();
    #pragma unroll
    for (int j = 0; j < 32; j += 8)
        g_featT[((size_t)b * NN + n0 + ty + j) * CC + c0 + tx] = t[tx][ty + j];
}

// ---------------------------------------------------------------------------
// K2: ball query, warp per query. First K in-index-order neighbors, pad first.
// ---------------------------------------------------------------------------
__global__ void k_ballquery(const float* __restrict__ xyz) {
    __shared__ int sf[8][KK];
    int w   = (blockIdx.x * blockDim.x + threadIdx.x) >> 5;  // global query
    int lid = threadIdx.x & 31;
    int wl  = threadIdx.x >> 5;
    int b = w / MM;
    float qx = g_newxyz[w*3+0], qy = g_newxyz[w*3+1], qz = g_newxyz[w*3+2];
    const float* base = xyz + (size_t)b * NN * 3;
    int cnt = 0;
    for (int n0 = 0; n0 < NN && cnt < KK; n0 += 32) {
        int n = n0 + lid;
        float dx = base[n*3+0] - qx;
        float dy = base[n*3+1] - qy;
        float dz = base[n*3+2] - qz;
        float d2 = dx*dx + dy*dy + dz*dz;
        bool within = d2 < RAD2;
        unsigned bal = __ballot_sync(0xffffffffu, within);
        if (within) {
            int r = cnt + __popc(bal & ((1u << lid) - 1u));
            if (r < KK) sf[wl][r] = n;
        }
        cnt += __popc(bal);
    }
    __syncwarp();
    int pad = (cnt > 0) ? sf[wl][0] : 0;
    int v = (lid < cnt && lid < KK) ? sf[wl][lid] : pad;
    g_idx[w * KK + lid] = v;
}

// ---------------------------------------------------------------------------
// GEMM micro-kernel shared shape:
//   block = 256 threads, tile = 128(O) x 64(P), c-chunks of 32.
//   thread (to=t/16, tp=t%16) owns o=to*8..+7, p=tp*4..+3  => acc[8][4]
// ---------------------------------------------------------------------------

// GEMM1: fused gather. x row c<3: xyz[n]-q; c>=3: featT[b][n][c-3].
__global__ __launch_bounds__(256) void k_gemm1(const float* __restrict__ xyz,
                                               const float* __restrict__ W,
                                               const float* __restrict__ bias) {
    __shared__ float xs[32][68];
    __shared__ float ws[32][O1];
    __shared__ int   s_n[64];
    __shared__ float s_q[64][3];

    const int p0 = blockIdx.x * 64;
    const int t  = threadIdx.x;
    const int to = t >> 4, tp = t & 15;
    const int b  = p0 / (MM * KK);

    if (t < 64) {
        int p = p0 + t;
        s_n[t] = g_idx[p];
        int q = p / KK;
        s_q[t][0] = g_newxyz[q*3+0];
        s_q[t][1] = g_newxyz[q*3+1];
        s_q[t][2] = g_newxyz[q*3+2];
    }
    __syncthreads();

    float acc[8][4];
    #pragma unroll
    for (int i = 0; i < 8; i++)
        #pragma unroll
        for (int j = 0; j < 4; j++) acc[i][j] = 0.f;

    for (int cc = 0; cc < C1; cc += 32) {
        int clen = min(32, C1 - cc);
        // weights: ws[ci][o] = W[o*C1 + cc+ci]
        for (int i = t; i < clen * O1; i += 256) {
            int ci = i >> 7, o = i & 127;
            ws[ci][o] = W[o * C1 + cc + ci];
        }
        // x tile gather: warp wl handles 8 points, lane = channel-in-chunk
        {
            int wl = t >> 5, lid = t & 31;
            int c = cc + lid;
            #pragma unroll
            for (int pi = 0; pi < 8; pi++) {
                int pl = wl * 8 + pi;
                if (lid < clen) {
                    int n = s_n[pl];
                    float v;
                    if (c < 3) v = xyz[((size_t)b * NN + n) * 3 + c] - s_q[pl][c];
                    else       v = g_featT[((size_t)b * NN + n) * CC + (c - 3)];
                    xs[lid][pl] = v;
                }
            }
        }
        __syncthreads();
        if (clen == 32) {
            #pragma unroll
            for (int ci = 0; ci < 32; ci++) {
                float wv[8], xv[4];
                *(float4*)&wv[0] = *(const float4*)&ws[ci][to*8];
                *(float4*)&wv[4] = *(const float4*)&ws[ci][to*8+4];
                *(float4*)&xv[0] = *(const float4*)&xs[ci][tp*4];
                #pragma unroll
                for (int i = 0; i < 8; i++)
                    #pragma unroll
                    for (int j = 0; j < 4; j++)
                        acc[i][j] = fmaf(wv[i], xv[j], acc[i][j]);
            }
        } else {
            for (int ci = 0; ci < clen; ci++) {
                float wv[8], xv[4];
                *(float4*)&wv[0] = *(const float4*)&ws[ci][to*8];
                *(float4*)&wv[4] = *(const float4*)&ws[ci][to*8+4];
                *(float4*)&xv[0] = *(const float4*)&xs[ci][tp*4];
                #pragma unroll
                for (int i = 0; i < 8; i++)
                    #pragma unroll
                    for (int j = 0; j < 4; j++)
                        acc[i][j] = fmaf(wv[i], xv[j], acc[i][j]);
            }
        }
        __syncthreads();
    }
    #pragma unroll
    for (int i = 0; i < 8; i++) {
        int o = to * 8 + i;
        float bs = bias[o];
        float4 v = make_float4(acc[i][0]+bs, acc[i][1]+bs, acc[i][2]+bs, acc[i][3]+bs);
        *(float4*)&g_y1[(size_t)o * PP + p0 + tp*4] = v;
    }
}

// GEMM2/3: x = relu(a*yin + b) applied at SMEM load. CIN = 128.
__global__ __launch_bounds__(256) void k_gemm_bn(const float* __restrict__ yin,
                                                 const float2* __restrict__ ab,
                                                 const float* __restrict__ W,
                                                 const float* __restrict__ bias,
                                                 float* __restrict__ yout) {
    __shared__ float xs[32][68];
    __shared__ float ws[32][128];
    const int p0   = blockIdx.x * 64;
    const int oOff = blockIdx.y * 128;
    const int t  = threadIdx.x;
    const int to = t >> 4, tp = t & 15;

    float acc[8][4];
    #pragma unroll
    for (int i = 0; i < 8; i++)
        #pragma unroll
        for (int j = 0; j < 4; j++) acc[i][j] = 0.f;

    for (int cc = 0; cc < CC; cc += 32) {
        for (int i = t; i < 32 * 128; i += 256) {
            int ci = i >> 7, o = i & 127;
            ws[ci][o] = W[(oOff + o) * CC + cc + ci];
        }
        #pragma unroll
        for (int pass = 0; pass < 8; pass++) {
            int ci = (t >> 6) + pass * 4;
            int pl = t & 63;
            int c = cc + ci;
            float2 s = ab[c];
            float v = yin[(size_t)c * PP + p0 + pl];
            xs[ci][pl] = fmaxf(fmaf(v, s.x, s.y), 0.f);
        }
        __syncthreads();
        #pragma unroll
        for (int ci = 0; ci < 32; ci++) {
            float wv[8], xv[4];
            *(float4*)&wv[0] = *(const float4*)&ws[ci][to*8];
            *(float4*)&wv[4] = *(const float4*)&ws[ci][to*8+4];
            *(float4*)&xv[0] = *(const float4*)&xs[ci][tp*4];
            #pragma unroll
            for (int i = 0; i < 8; i++)
                #pragma unroll
                for (int j = 0; j < 4; j++)
                    acc[i][j] = fmaf(wv[i], xv[j], acc[i][j]);
        }
        __syncthreads();
    }
    #pragma unroll
    for (int i = 0; i < 8; i++) {
        int o = oOff + to * 8 + i;
        float bs = bias[o];
        float4 v = make_float4(acc[i][0]+bs, acc[i][1]+bs, acc[i][2]+bs, acc[i][3]+bs);
        *(float4*)&yout[(size_t)o * PP + p0 + tp*4] = v;
    }
}

// ---------------------------------------------------------------------------
// BN stats: one block per channel, deterministic tree reduction.
// Produces affine (a, b): bn(x) = a*x + b
// ---------------------------------------------------------------------------
__global__ __launch_bounds__(512) void k_bnstats(const float* __restrict__ y,
                                                 const float* __restrict__ gamma,
                                                 const float* __restrict__ beta,
                                                 float2* __restrict__ ab) {
    __shared__ float2 red[512];
    int c = blockIdx.x;
    int t = threadIdx.x;
    const float4* row = (const float4*)(y + (size_t)c * PP);
    float s = 0.f, s2 = 0.f;
    for (int i = t; i < PP / 4; i += 512) {
        float4 v = row[i];
        s  += v.x + v.y + v.z + v.w;
        s2 += v.x*v.x + v.y*v.y + v.z*v.z + v.w*v.w;
    }
    red[t] = make_float2(s, s2);
    __syncthreads();
    for (int st = 256; st > 0; st >>= 1) {
        if (t < st) {
            red[t].x += red[t + st].x;
            red[t].y += red[t + st].y;
        }
        __syncthreads();
    }
    if (t == 0) {
        float mean = red[0].x / (float)PP;
        float var  = red[0].y / (float)PP - mean * mean;
        float a = gamma[c] * rsqrtf(var + EPSV);
        ab[c] = make_float2(a, beta[c] - a * mean);
    }
}

// ---------------------------------------------------------------------------
// Final: apply BN3+ReLU and max over K; write new_features region of output
// ---------------------------------------------------------------------------
__global__ void k_maxpool(float* __restrict__ out) {
    int i = blockIdx.x * blockDim.x + threadIdx.x;  // over B*O3*M
    if (i >= BB * O3 * MM) return;
    int m = i % MM;
    int o = (i / MM) % O3;
    int b = i / (MM * O3);
    float2 s = g_ab3[o];
    const float4* p = (const float4*)(g_y3 + (size_t)o * PP + (size_t)(b * MM + m) * KK);
    float mx = -INFINITY;
    #pragma unroll
    for (int j = 0; j < 8; j++) {
        float4 v = p[j];
        mx = fmaxf(mx, fmaf(v.x, s.x, s.y));
        mx = fmaxf(mx, fmaf(v.y, s.x, s.y));
        mx = fmaxf(mx, fmaf(v.z, s.x, s.y));
        mx = fmaxf(mx, fmaf(v.w, s.x, s.y));
    }
    out[BB * MM * 3 + i] = fmaxf(mx, 0.f);
}

// ---------------------------------------------------------------------------
extern "C" void kernel_launch(void* const* d_in, const int* in_sizes, int n_in,
                              void* d_out, int out_size) {
    const float* xyz     = (const float*)d_in[0];
    const float* feat    = (const float*)d_in[1];
    const int*   indices = (const int*)d_in[2];
    const float* w1 = (const float*)d_in[3];
    const float* b1 = (const float*)d_in[4];
    const float* g1 = (const float*)d_in[5];
    const float* be1 = (const float*)d_in[6];
    const float* w2 = (const float*)d_in[7];
    const float* b2 = (const float*)d_in[8];
    const float* g2 = (const float*)d_in[9];
    const float* be2 = (const float*)d_in[10];
    const float* w3 = (const float*)d_in[11];
    const float* b3 = (const float*)d_in[12];
    const float* g3 = (const float*)d_in[13];
    const float* be3 = (const float*)d_in[14];
    float* out = (float*)d_out;

    float2* ab1; cudaGetSymbolAddress((void**)&ab1, g_ab1);
    float2* ab2; cudaGetSymbolAddress((void**)&ab2, g_ab2);
    float2* ab3; cudaGetSymbolAddress((void**)&ab3, g_ab3);
    float* y1; cudaGetSymbolAddress((void**)&y1, g_y1);
    float* y2; cudaGetSymbolAddress((void**)&y2, g_y2);
    float* y3; cudaGetSymbolAddress((void**)&y3, g_y3);

    k_gather_newxyz<<<(BB*MM + 255) / 256, 256>>>(xyz, indices, out);
    k_transpose_feat<<<dim3(NN/32, CC/32, BB), dim3(32, 8)>>>(feat);
    k_ballquery<<<(BB*MM) / 8, 256>>>(xyz);
    k_gemm1<<<PP/64, 256>>>(xyz, w1, b1);
    k_bnstats<<<O1, 512>>>(y1, g1, be1, ab1);
    k_gemm_bn<<<dim3(PP/64, 1), 256>>>(y1, ab1, w2, b2, y2);
    k_bnstats<<<O2, 512>>>(y2, g2, be2, ab2);
    k_gemm_bn<<<dim3(PP/64, 2), 256>>>(y2, ab2, w3, b3, y3);
    k_bnstats<<<O3, 512>>>(y3, g3, be3, ab3);
    k_maxpool<<<(BB*O3*MM + 255) / 256, 256>>>(out);
}

// round 3
// speedup vs baseline: 1.5872x; 1.5872x over previous
#include <cuda_runtime.h>
#include <cstdint>
#include <math.h>

// Problem constants
#define BB 4
#define NN 16384
#define CC 128
#define MM 1024
#define KK 32
#define PP (BB*MM*KK)     // 131072 points
#define C1 131
#define O1 128
#define O2 128
#define O3 256
#define RAD2 0.16f
#define EPSV 1e-5f
#define NT (PP/128)       // 1024 p-tiles of 128

// ---------------------------------------------------------------------------
// Scratch (static device globals)
// y tensors CHANNEL-MAJOR: y[c][p]
// ---------------------------------------------------------------------------
__device__ float  g_featT[(size_t)BB*NN*CC];
__device__ float  g_newxyz[BB*MM*3];
__device__ int    g_idx[BB*MM*KK];
__device__ float  g_y1[(size_t)O1*PP];
__device__ float  g_y2[(size_t)O2*PP];
__device__ float  g_w1t[C1*O1];
__device__ float  g_w2t[CC*O2];
__device__ float  g_w3t[CC*O3];
__device__ float2 g_ab1[O1];
__device__ float2 g_ab2[O2];
__device__ float2 g_ab3[O3];
__device__ float2 g_part1[O1*NT];   // [o][tile]
__device__ float2 g_part2[O2*NT];
__device__ float2 g_part3[O3*NT];
__device__ float  g_mx[(size_t)BB*MM*O3];   // pre-BN max over K, [gm][o]
__device__ float  g_mn[(size_t)BB*MM*O3];   // pre-BN min over K

// ---------------------------------------------------------------------------
// K0: gather new_xyz; write output region [0, B*M*3)
// ---------------------------------------------------------------------------
__global__ void k_gather_newxyz(const float* __restrict__ xyz,
                                const int* __restrict__ indices,
                                float* __restrict__ out) {
    int i = blockIdx.x * blockDim.x + threadIdx.x;
    if (i >= BB * MM) return;
    int b = i / MM;
    int n = indices[i];
    const float* src = xyz + ((size_t)b * NN + n) * 3;
    float x = src[0], y = src[1], z = src[2];
    g_newxyz[i*3+0] = x; g_newxyz[i*3+1] = y; g_newxyz[i*3+2] = z;
    out[i*3+0] = x; out[i*3+1] = y; out[i*3+2] = z;
}

// ---------------------------------------------------------------------------
// K1: transpose features (B,C,N) -> (B,N,C)
// ---------------------------------------------------------------------------
__global__ void k_transpose_feat(const float* __restrict__ f) {
    __shared__ float t[32][33];
    int b  = blockIdx.z;
    int c0 = blockIdx.y * 32;
    int n0 = blockIdx.x * 32;
    int tx = threadIdx.x, ty = threadIdx.y;  // 32 x 8
    #pragma unroll
    for (int j = 0; j < 32; j += 8)
        t[ty + j][tx] = f[((size_t)b * CC + c0 + ty + j) * NN + n0 + tx];
    __syncthreads();
    #pragma unroll
    for (int j = 0; j < 32; j += 8)
        g_featT[((size_t)b * NN + n0 + ty + j) * CC + c0 + tx] = t[tx][ty + j];
}

// ---------------------------------------------------------------------------
// K1b: transpose weights (O,C) -> (C,O)
// ---------------------------------------------------------------------------
__global__ void k_wtrans(const float* __restrict__ w, float* __restrict__ wt,
                         int O, int Cn) {
    int i = blockIdx.x * 256 + threadIdx.x;
    if (i < O * Cn) {
        int o = i / Cn, c = i % Cn;
        wt[c * O + o] = w[i];
    }
}

// ---------------------------------------------------------------------------
// K2: ball query, warp per query
// ---------------------------------------------------------------------------
__global__ void k_ballquery(const float* __restrict__ xyz) {
    __shared__ int sf[8][KK];
    int w   = (blockIdx.x * blockDim.x + threadIdx.x) >> 5;
    int lid = threadIdx.x & 31;
    int wl  = threadIdx.x >> 5;
    int b = w / MM;
    float qx = g_newxyz[w*3+0], qy = g_newxyz[w*3+1], qz = g_newxyz[w*3+2];
    const float* base = xyz + (size_t)b * NN * 3;
    int cnt = 0;
    for (int n0 = 0; n0 < NN && cnt < KK; n0 += 32) {
        int n = n0 + lid;
        float dx = base[n*3+0] - qx;
        float dy = base[n*3+1] - qy;
        float dz = base[n*3+2] - qz;
        float d2 = dx*dx + dy*dy + dz*dz;
        bool within = d2 < RAD2;
        unsigned bal = __ballot_sync(0xffffffffu, within);
        if (within) {
            int r = cnt + __popc(bal & ((1u << lid) - 1u));
            if (r < KK) sf[wl][r] = n;
        }
        cnt += __popc(bal);
    }
    __syncwarp();
    int pad = (cnt > 0) ? sf[wl][0] : 0;
    int v = (lid < cnt && lid < KK) ? sf[wl][lid] : pad;
    g_idx[w * KK + lid] = v;
}

// ---------------------------------------------------------------------------
// Shared epilogue pieces (device inline)
// Thread (to=t>>4, tp=t&15) owns o = oBase+to*8+{0..7}, p = p0+tp*8+{0..7}
// ---------------------------------------------------------------------------
__device__ __forceinline__ void epilogue_partials(float v[8][8], int o0,
                                                  int tile, int tp,
                                                  float2* __restrict__ part) {
    float s[8], s2[8];
    #pragma unroll
    for (int i = 0; i < 8; i++) {
        float a = 0.f, a2 = 0.f;
        #pragma unroll
        for (int j = 0; j < 8; j++) { a += v[i][j]; a2 += v[i][j]*v[i][j]; }
        s[i] = a; s2[i] = a2;
    }
    #pragma unroll
    for (int d = 1; d < 16; d <<= 1) {
        #pragma unroll
        for (int i = 0; i < 8; i++) {
            s[i]  += __shfl_xor_sync(0xffffffffu, s[i],  d);
            s2[i] += __shfl_xor_sync(0xffffffffu, s2[i], d);
        }
    }
    if (tp == 0) {
        #pragma unroll
        for (int i = 0; i < 8; i++)
            part[(size_t)(o0 + i) * NT + tile] = make_float2(s[i], s2[i]);
    }
}

// ---------------------------------------------------------------------------
// GEMM1: fused gather, SIMT 128x128 tile. y1[o][p] += partials.
// ---------------------------------------------------------------------------
__global__ __launch_bounds__(256, 2) void k_gemm1(const float* __restrict__ xyz,
                                                  const float* __restrict__ bias) {
    __shared__ float ws[16][128];
    __shared__ float xs[16][128];
    __shared__ int   s_n[128];
    __shared__ float s_q[128][3];

    const int p0 = blockIdx.x * 128;
    const int t  = threadIdx.x;
    const int to = t >> 4, tp = t & 15;
    const int b  = p0 / (MM * KK);

    if (t < 128) {
        int p = p0 + t;
        s_n[t] = g_idx[p];
        int q = p / KK;
        s_q[t][0] = g_newxyz[q*3+0];
        s_q[t][1] = g_newxyz[q*3+1];
        s_q[t][2] = g_newxyz[q*3+2];
    }
    __syncthreads();

    float acc[8][8];
    #pragma unroll
    for (int i = 0; i < 8; i++)
        #pragma unroll
        for (int j = 0; j < 8; j++) acc[i][j] = 0.f;

    // ---- chunk 0: xyz channels (clen = 3) ----
    {
        if (t < 96) {
            int ci = t >> 5, o = (t & 31) * 4;
            *(float4*)&ws[ci][o] = *(const float4*)&g_w1t[ci*O1 + o];
        }
        if (t < 128) {
            int n = s_n[t];
            const float* px = xyz + ((size_t)b * NN + n) * 3;
            xs[0][t] = px[0] - s_q[t][0];
            xs[1][t] = px[1] - s_q[t][1];
            xs[2][t] = px[2] - s_q[t][2];
        }
        __syncthreads();
        #pragma unroll
        for (int ci = 0; ci < 3; ci++) {
            float4 w0 = *(float4*)&ws[ci][to*8];
            float4 w1 = *(float4*)&ws[ci][to*8+4];
            float4 x0 = *(float4*)&xs[ci][tp*8];
            float4 x1 = *(float4*)&xs[ci][tp*8+4];
            float wv[8] = {w0.x,w0.y,w0.z,w0.w,w1.x,w1.y,w1.z,w1.w};
            float xv[8] = {x0.x,x0.y,x0.z,x0.w,x1.x,x1.y,x1.z,x1.w};
            #pragma unroll
            for (int i = 0; i < 8; i++)
                #pragma unroll
                for (int j = 0; j < 8; j++)
                    acc[i][j] = fmaf(wv[i], xv[j], acc[i][j]);
        }
        __syncthreads();
    }

    // ---- chunks of 16 feature channels: c = 3 + 16*ch ----
    for (int ch = 0; ch < 8; ch++) {
        const int c0 = 3 + ch * 16;
        // weights
        #pragma unroll
        for (int i = 0; i < 2; i++) {
            int idx = t + i*256;
            int ci = idx >> 5, o = (idx & 31) * 4;
            *(float4*)&ws[ci][o] = *(const float4*)&g_w1t[(c0 + ci)*O1 + o];
        }
        // gather: thread t -> point p = t>>1, channel-segment (t&1)*8
        {
            int p = t >> 1, cseg = (t & 1) * 8;
            int n = s_n[p];
            const float* fp = g_featT + ((size_t)b * NN + n) * CC + (c0 - 3) + cseg;
            float4 f0 = *(const float4*)fp;
            float4 f1 = *(const float4*)(fp + 4);
            xs[cseg+0][p] = f0.x; xs[cseg+1][p] = f0.y;
            xs[cseg+2][p] = f0.z; xs[cseg+3][p] = f0.w;
            xs[cseg+4][p] = f1.x; xs[cseg+5][p] = f1.y;
            xs[cseg+6][p] = f1.z; xs[cseg+7][p] = f1.w;
        }
        __syncthreads();
        #pragma unroll
        for (int ci = 0; ci < 16; ci++) {
            float4 w0 = *(float4*)&ws[ci][to*8];
            float4 w1 = *(float4*)&ws[ci][to*8+4];
            float4 x0 = *(float4*)&xs[ci][tp*8];
            float4 x1 = *(float4*)&xs[ci][tp*8+4];
            float wv[8] = {w0.x,w0.y,w0.z,w0.w,w1.x,w1.y,w1.z,w1.w};
            float xv[8] = {x0.x,x0.y,x0.z,x0.w,x1.x,x1.y,x1.z,x1.w};
            #pragma unroll
            for (int i = 0; i < 8; i++)
                #pragma unroll
                for (int j = 0; j < 8; j++)
                    acc[i][j] = fmaf(wv[i], xv[j], acc[i][j]);
        }
        __syncthreads();
    }

    // epilogue: bias, write y1[o][p], partials
    const int o0 = to * 8;
    #pragma unroll
    for (int i = 0; i < 8; i++) {
        float bs = bias[o0 + i];
        #pragma unroll
        for (int j = 0; j < 8; j++) acc[i][j] += bs;
        *(float4*)&g_y1[(size_t)(o0+i)*PP + p0 + tp*8]     = *(float4*)&acc[i][0];
        *(float4*)&g_y1[(size_t)(o0+i)*PP + p0 + tp*8 + 4] = *(float4*)&acc[i][4];
    }
    epilogue_partials(acc, o0, blockIdx.x, tp, g_part1);
}

// ---------------------------------------------------------------------------
// BN finalize: reduce [o][tile] partials -> affine (a,b)
// ---------------------------------------------------------------------------
__global__ __launch_bounds__(256) void k_bnfinal(const float2* __restrict__ part,
                                                 const float* __restrict__ gamma,
                                                 const float* __restrict__ beta,
                                                 float2* __restrict__ abo) {
    __shared__ float2 red[256];
    int o = blockIdx.x, t = threadIdx.x;
    float s = 0.f, s2 = 0.f;
    for (int i = t; i < NT; i += 256) {
        float2 v = part[(size_t)o * NT + i];
        s += v.x; s2 += v.y;
    }
    red[t] = make_float2(s, s2);
    __syncthreads();
    for (int st = 128; st > 0; st >>= 1) {
        if (t < st) { red[t].x += red[t+st].x; red[t].y += red[t+st].y; }
        __syncthreads();
    }
    if (t == 0) {
        float mean = red[0].x / (float)PP;
        float var  = red[0].y / (float)PP - mean * mean;
        float a = gamma[o] * rsqrtf(var + EPSV);
        abo[o] = make_float2(a, beta[o] - a * mean);
    }
}

// ---------------------------------------------------------------------------
// GEMM mid (layer 2): relu(a*y1+b) @ W2 -> y2[o][p], + partials.
// 128x128 tile, k-chunks of 16, register double-buffered.
// ---------------------------------------------------------------------------
__global__ __launch_bounds__(256, 2) void k_gemm_mid(const float* __restrict__ yin,
                                                     const float2* __restrict__ ab,
                                                     const float* __restrict__ wt,
                                                     const float* __restrict__ bias,
                                                     float* __restrict__ yout,
                                                     float2* __restrict__ part) {
    __shared__ float ws[16][128];
    __shared__ float xs[16][128];
    const int p0 = blockIdx.x * 128;
    const int t  = threadIdx.x;
    const int to = t >> 4, tp = t & 15;

    float acc[8][8];
    #pragma unroll
    for (int i = 0; i < 8; i++)
        #pragma unroll
        for (int j = 0; j < 8; j++) acc[i][j] = 0.f;

    float4 wr[2], xr[2];
    // prologue: load chunk 0
    #pragma unroll
    for (int i = 0; i < 2; i++) {
        int idx = t + i*256;
        int ci = idx >> 5, q4 = (idx & 31) * 4;
        wr[i] = *(const float4*)&wt[(size_t)ci * O2 + q4];
        float4 v = *(const float4*)&yin[(size_t)ci * PP + p0 + q4];
        float2 s = ab[ci];
        v.x = fmaxf(fmaf(v.x, s.x, s.y), 0.f);
        v.y = fmaxf(fmaf(v.y, s.x, s.y), 0.f);
        v.z = fmaxf(fmaf(v.z, s.x, s.y), 0.f);
        v.w = fmaxf(fmaf(v.w, s.x, s.y), 0.f);
        xr[i] = v;
    }

    for (int ch = 0; ch < 8; ch++) {
        #pragma unroll
        for (int i = 0; i < 2; i++) {
            int idx = t + i*256;
            int ci = idx >> 5, q4 = (idx & 31) * 4;
            *(float4*)&ws[ci][q4] = wr[i];
            *(float4*)&xs[ci][q4] = xr[i];
        }
        __syncthreads();
        if (ch < 7) {
            int cbase = (ch + 1) * 16;
            #pragma unroll
            for (int i = 0; i < 2; i++) {
                int idx = t + i*256;
                int ci = idx >> 5, q4 = (idx & 31) * 4;
                int c = cbase + ci;
                wr[i] = *(const float4*)&wt[(size_t)c * O2 + q4];
                float4 v = *(const float4*)&yin[(size_t)c * PP + p0 + q4];
                float2 s = ab[c];
                v.x = fmaxf(fmaf(v.x, s.x, s.y), 0.f);
                v.y = fmaxf(fmaf(v.y, s.x, s.y), 0.f);
                v.z = fmaxf(fmaf(v.z, s.x, s.y), 0.f);
                v.w = fmaxf(fmaf(v.w, s.x, s.y), 0.f);
                xr[i] = v;
            }
        }
        #pragma unroll
        for (int ci = 0; ci < 16; ci++) {
            float4 w0 = *(float4*)&ws[ci][to*8];
            float4 w1 = *(float4*)&ws[ci][to*8+4];
            float4 x0 = *(float4*)&xs[ci][tp*8];
            float4 x1 = *(float4*)&xs[ci][tp*8+4];
            float wv[8] = {w0.x,w0.y,w0.z,w0.w,w1.x,w1.y,w1.z,w1.w};
            float xv[8] = {x0.x,x0.y,x0.z,x0.w,x1.x,x1.y,x1.z,x1.w};
            #pragma unroll
            for (int i = 0; i < 8; i++)
                #pragma unroll
                for (int j = 0; j < 8; j++)
                    acc[i][j] = fmaf(wv[i], xv[j], acc[i][j]);
        }
        __syncthreads();
    }

    const int o0 = to * 8;
    #pragma unroll
    for (int i = 0; i < 8; i++) {
        float bs = bias[o0 + i];
        #pragma unroll
        for (int j = 0; j < 8; j++) acc[i][j] += bs;
        *(float4*)&yout[(size_t)(o0+i)*PP + p0 + tp*8]     = *(float4*)&acc[i][0];
        *(float4*)&yout[(size_t)(o0+i)*PP + p0 + tp*8 + 4] = *(float4*)&acc[i][4];
    }
    epilogue_partials(acc, o0, blockIdx.x, tp, part);
}

// ---------------------------------------------------------------------------
// GEMM last (layer 3): relu(a*y2+b) @ W3. NO y3 output.
// Emits partials + per-(group, o) max/min over K=32 (pre-BN).
// grid (PP/128, O3/128)
// ---------------------------------------------------------------------------
__global__ __launch_bounds__(256, 2) void k_gemm_last(const float* __restrict__ yin,
                                                      const float2* __restrict__ ab,
                                                      const float* __restrict__ wt,
                                                      const float* __restrict__ bias) {
    __shared__ float ws[16][128];
    __shared__ float xs[16][128];
    const int p0   = blockIdx.x * 128;
    const int oOff = blockIdx.y * 128;
    const int t  = threadIdx.x;
    const int to = t >> 4, tp = t & 15;

    float acc[8][8];
    #pragma unroll
    for (int i = 0; i < 8; i++)
        #pragma unroll
        for (int j = 0; j < 8; j++) acc[i][j] = 0.f;

    float4 wr[2], xr[2];
    #pragma unroll
    for (int i = 0; i < 2; i++) {
        int idx = t + i*256;
        int ci = idx >> 5, q4 = (idx & 31) * 4;
        wr[i] = *(const float4*)&wt[(size_t)ci * O3 + oOff + q4];
        float4 v = *(const float4*)&yin[(size_t)ci * PP + p0 + q4];
        float2 s = ab[ci];
        v.x = fmaxf(fmaf(v.x, s.x, s.y), 0.f);
        v.y = fmaxf(fmaf(v.y, s.x, s.y), 0.f);
        v.z = fmaxf(fmaf(v.z, s.x, s.y), 0.f);
        v.w = fmaxf(fmaf(v.w, s.x, s.y), 0.f);
        xr[i] = v;
    }

    for (int ch = 0; ch < 8; ch++) {
        #pragma unroll
        for (int i = 0; i < 2; i++) {
            int idx = t + i*256;
            int ci = idx >> 5, q4 = (idx & 31) * 4;
            *(float4*)&ws[ci][q4] = wr[i];
            *(float4*)&xs[ci][q4] = xr[i];
        }
        __syncthreads();
        if (ch < 7) {
            int cbase = (ch + 1) * 16;
            #pragma unroll
            for (int i = 0; i < 2; i++) {
                int idx = t + i*256;
                int ci = idx >> 5, q4 = (idx & 31) * 4;
                int c = cbase + ci;
                wr[i] = *(const float4*)&wt[(size_t)c * O3 + oOff + q4];
                float4 v = *(const float4*)&yin[(size_t)c * PP + p0 + q4];
                float2 s = ab[c];
                v.x = fmaxf(fmaf(v.x, s.x, s.y), 0.f);
                v.y = fmaxf(fmaf(v.y, s.x, s.y), 0.f);
                v.z = fmaxf(fmaf(v.z, s.x, s.y), 0.f);
                v.w = fmaxf(fmaf(v.w, s.x, s.y), 0.f);
                xr[i] = v;
            }
        }
        #pragma unroll
        for (int ci = 0; ci < 16; ci++) {
            float4 w0 = *(float4*)&ws[ci][to*8];
            float4 w1 = *(float4*)&ws[ci][to*8+4];
            float4 x0 = *(float4*)&xs[ci][tp*8];
            float4 x1 = *(float4*)&xs[ci][tp*8+4];
            float wv[8] = {w0.x,w0.y,w0.z,w0.w,w1.x,w1.y,w1.z,w1.w};
            float xv[8] = {x0.x,x0.y,x0.z,x0.w,x1.x,x1.y,x1.z,x1.w};
            #pragma unroll
            for (int i = 0; i < 8; i++)
                #pragma unroll
                for (int j = 0; j < 8; j++)
                    acc[i][j] = fmaf(wv[i], xv[j], acc[i][j]);
        }
        __syncthreads();
    }

    const int o0l = to * 8;
    const int o0  = oOff + o0l;
    #pragma unroll
    for (int i = 0; i < 8; i++) {
        float bs = bias[o0 + i];
        #pragma unroll
        for (int j = 0; j < 8; j++) acc[i][j] += bs;
    }
    // BN partials (global o index)
    epilogue_partials(acc, o0, blockIdx.x, tp, g_part3);

    // max/min over K=32: thread's 8 p are inside group (tp>>2); reduce 4 threads
    float mx[8], mn[8];
    #pragma unroll
    for (int i = 0; i < 8; i++) {
        float a = acc[i][0], b = acc[i][0];
        #pragma unroll
        for (int j = 1; j < 8; j++) {
            a = fmaxf(a, acc[i][j]);
            b = fminf(b, acc[i][j]);
        }
        mx[i] = a; mn[i] = b;
    }
    #pragma unroll
    for (int d = 1; d < 4; d <<= 1) {
        #pragma unroll
        for (int i = 0; i < 8; i++) {
            mx[i] = fmaxf(mx[i], __shfl_xor_sync(0xffffffffu, mx[i], d));
            mn[i] = fminf(mn[i], __shfl_xor_sync(0xffffffffu, mn[i], d));
        }
    }
    if ((tp & 3) == 0) {
        int gm = p0 / 32 + (tp >> 2);
        *(float4*)&g_mx[(size_t)gm * O3 + o0]     = *(float4*)&mx[0];
        *(float4*)&g_mx[(size_t)gm * O3 + o0 + 4] = *(float4*)&mx[4];
        *(float4*)&g_mn[(size_t)gm * O3 + o0]     = *(float4*)&mn[0];
        *(float4*)&g_mn[(size_t)gm * O3 + o0 + 4] = *(float4*)&mn[4];
    }
}

// ---------------------------------------------------------------------------
// Finalize: new_features[b][o][m] = relu(a*ext + b), ext = max/min by sign(a).
// Transposed through smem for coalesced I/O.
// ---------------------------------------------------------------------------
__global__ void k_finalize(float* __restrict__ out) {
    __shared__ float tile[32][33];
    int gm0 = blockIdx.x * 32;
    int o0  = blockIdx.y * 32;
    int tx = threadIdx.x, ty = threadIdx.y;  // 32 x 8
    #pragma unroll
    for (int j = 0; j < 32; j += 8) {
        int gm = gm0 + ty + j;
        int o  = o0 + tx;
        float2 s = g_ab3[o];
        float ext = (s.x >= 0.f) ? g_mx[(size_t)gm * O3 + o]
                                 : g_mn[(size_t)gm * O3 + o];
        tile[tx][ty + j] = fmaxf(fmaf(ext, s.x, s.y), 0.f);
    }
    __syncthreads();
    int b = gm0 / MM;
    int m0 = gm0 - b * MM;
    #pragma unroll
    for (int j = 0; j < 32; j += 8) {
        int o = o0 + ty + j;
        out[(size_t)BB*MM*3 + ((size_t)(b * O3 + o)) * MM + m0 + tx] = tile[ty + j][tx];
    }
}

// ---------------------------------------------------------------------------
extern "C" void kernel_launch(void* const* d_in, const int* in_sizes, int n_in,
                              void* d_out, int out_size) {
    const float* xyz     = (const float*)d_in[0];
    const float* feat    = (const float*)d_in[1];
    const int*   indices = (const int*)d_in[2];
    const float* w1 = (const float*)d_in[3];
    const float* b1 = (const float*)d_in[4];
    const float* g1 = (const float*)d_in[5];
    const float* be1 = (const float*)d_in[6];
    const float* w2 = (const float*)d_in[7];
    const float* b2 = (const float*)d_in[8];
    const float* g2 = (const float*)d_in[9];
    const float* be2 = (const float*)d_in[10];
    const float* w3 = (const float*)d_in[11];
    const float* b3 = (const float*)d_in[12];
    const float* g3 = (const float*)d_in[13];
    const float* be3 = (const float*)d_in[14];
    float* out = (float*)d_out;

    float* w1t; cudaGetSymbolAddress((void**)&w1t, g_w1t);
    float* w2t; cudaGetSymbolAddress((void**)&w2t, g_w2t);
    float* w3t; cudaGetSymbolAddress((void**)&w3t, g_w3t);
    float* y1; cudaGetSymbolAddress((void**)&y1, g_y1);
    float* y2; cudaGetSymbolAddress((void**)&y2, g_y2);
    float2* ab1; cudaGetSymbolAddress((void**)&ab1, g_ab1);
    float2* ab2; cudaGetSymbolAddress((void**)&ab2, g_ab2);
    float2* ab3; cudaGetSymbolAddress((void**)&ab3, g_ab3);
    float2* part1; cudaGetSymbolAddress((void**)&part1, g_part1);
    float2* part2; cudaGetSymbolAddress((void**)&part2, g_part2);
    float2* part3; cudaGetSymbolAddress((void**)&part3, g_part3);

    k_gather_newxyz<<<(BB*MM + 255) / 256, 256>>>(xyz, indices, out);
    k_transpose_feat<<<dim3(NN/32, CC/32, BB), dim3(32, 8)>>>(feat);
    k_wtrans<<<(O1*C1 + 255)/256, 256>>>(w1, w1t, O1, C1);
    k_wtrans<<<(O2*CC + 255)/256, 256>>>(w2, w2t, O2, CC);
    k_wtrans<<<(O3*CC + 255)/256, 256>>>(w3, w3t, O3, CC);
    k_ballquery<<<(BB*MM) / 8, 256>>>(xyz);
    k_gemm1<<<PP/128, 256>>>(xyz, b1);
    k_bnfinal<<<O1, 256>>>(part1, g1, be1, ab1);
    k_gemm_mid<<<PP/128, 256>>>(y1, ab1, w2t, b2, y2, part2);
    k_bnfinal<<<O2, 256>>>(part2, g2, be2, ab2);
    k_gemm_last<<<dim3(PP/128, O3/128), 256>>>(y2, ab2, w3t, b3);
    k_bnfinal<<<O3, 256>>>(part3, g3, be3, ab3);
    k_finalize<<<dim3(BB*MM/32, O3/32), dim3(32, 8)>>>(out);
}

// round 4
// speedup vs baseline: 1.7935x; 1.1299x over previous
#include <cuda_runtime.h>
#include <cuda_bf16.h>
#include <cstdint>
#include <math.h>

// Problem constants
#define BB 4
#define NN 16384
#define CC 128
#define MM 1024
#define KK 32
#define PP (BB*MM*KK)     // 131072 points
#define C1 131
#define O1 128
#define O2 128
#define O3 256
#define RAD2 0.16f
#define EPSV 1e-5f
#define NT (PP/128)       // 1024 p-tiles of 128 (gemm1 partials)
#define NT4 (PP/32)       // 4096 per-warp partial slots (mma gemms)

// ---------------------------------------------------------------------------
// Scratch
// ---------------------------------------------------------------------------
__device__ float  g_featT[(size_t)BB*NN*CC];
__device__ float  g_newxyz[BB*MM*3];
__device__ int    g_idx[BB*MM*KK];
__device__ float  g_y1[(size_t)O1*PP];
__device__ float  g_y2[(size_t)O2*PP];
__device__ float  g_w1t[C1*O1];
__device__ float2 g_ab1[O1];
__device__ float2 g_ab2[O2];
__device__ float2 g_ab3[O3];
__device__ float2 g_part1[O1*NT];
__device__ float2 g_part2[(size_t)O2*NT4];
__device__ float2 g_part3[(size_t)O3*NT4];
__device__ float  g_mx[(size_t)BB*MM*O3];
__device__ float  g_mn[(size_t)BB*MM*O3];

__device__ __forceinline__ uint32_t smem_u32(const void* p) {
    uint32_t a;
    asm("{ .reg .u64 tmp; cvta.to.shared.u64 tmp, %1; cvt.u32.u64 %0, tmp; }"
        : "=r"(a) : "l"(p));
    return a;
}

// ---------------------------------------------------------------------------
// K0: gather new_xyz
// ---------------------------------------------------------------------------
__global__ void k_gather_newxyz(const float* __restrict__ xyz,
                                const int* __restrict__ indices,
                                float* __restrict__ out) {
    int i = blockIdx.x * blockDim.x + threadIdx.x;
    if (i >= BB * MM) return;
    int b = i / MM;
    int n = indices[i];
    const float* src = xyz + ((size_t)b * NN + n) * 3;
    float x = src[0], y = src[1], z = src[2];
    g_newxyz[i*3+0] = x; g_newxyz[i*3+1] = y; g_newxyz[i*3+2] = z;
    out[i*3+0] = x; out[i*3+1] = y; out[i*3+2] = z;
}

// ---------------------------------------------------------------------------
// K1: transpose features (B,C,N) -> (B,N,C)
// ---------------------------------------------------------------------------
__global__ void k_transpose_feat(const float* __restrict__ f) {
    __shared__ float t[32][33];
    int b  = blockIdx.z;
    int c0 = blockIdx.y * 32;
    int n0 = blockIdx.x * 32;
    int tx = threadIdx.x, ty = threadIdx.y;
    #pragma unroll
    for (int j = 0; j < 32; j += 8)
        t[ty + j][tx] = f[((size_t)b * CC + c0 + ty + j) * NN + n0 + tx];
    __syncthreads();
    #pragma unroll
    for (int j = 0; j < 32; j += 8)
        g_featT[((size_t)b * NN + n0 + ty + j) * CC + c0 + tx] = t[tx][ty + j];
}

// K1b: transpose W1 (O,C)->(C,O)
__global__ void k_wtrans(const float* __restrict__ w, float* __restrict__ wt,
                         int O, int Cn) {
    int i = blockIdx.x * 256 + threadIdx.x;
    if (i < O * Cn) {
        int o = i / Cn, c = i % Cn;
        wt[c * O + o] = w[i];
    }
}

// ---------------------------------------------------------------------------
// K2: ball query
// ---------------------------------------------------------------------------
__global__ void k_ballquery(const float* __restrict__ xyz) {
    __shared__ int sf[8][KK];
    int w   = (blockIdx.x * blockDim.x + threadIdx.x) >> 5;
    int lid = threadIdx.x & 31;
    int wl  = threadIdx.x >> 5;
    int b = w / MM;
    float qx = g_newxyz[w*3+0], qy = g_newxyz[w*3+1], qz = g_newxyz[w*3+2];
    const float* base = xyz + (size_t)b * NN * 3;
    int cnt = 0;
    for (int n0 = 0; n0 < NN && cnt < KK; n0 += 32) {
        int n = n0 + lid;
        float dx = base[n*3+0] - qx;
        float dy = base[n*3+1] - qy;
        float dz = base[n*3+2] - qz;
        float d2 = dx*dx + dy*dy + dz*dz;
        bool within = d2 < RAD2;
        unsigned bal = __ballot_sync(0xffffffffu, within);
        if (within) {
            int r = cnt + __popc(bal & ((1u << lid) - 1u));
            if (r < KK) sf[wl][r] = n;
        }
        cnt += __popc(bal);
    }
    __syncwarp();
    int pad = (cnt > 0) ? sf[wl][0] : 0;
    int v = (lid < cnt && lid < KK) ? sf[wl][lid] : pad;
    g_idx[w * KK + lid] = v;
}

// ---------------------------------------------------------------------------
// gemm1 partials helper
// ---------------------------------------------------------------------------
__device__ __forceinline__ void epilogue_partials(float v[8][8], int o0,
                                                  int tile, int tp,
                                                  float2* __restrict__ part) {
    float s[8], s2[8];
    #pragma unroll
    for (int i = 0; i < 8; i++) {
        float a = 0.f, a2 = 0.f;
        #pragma unroll
        for (int j = 0; j < 8; j++) { a += v[i][j]; a2 += v[i][j]*v[i][j]; }
        s[i] = a; s2[i] = a2;
    }
    #pragma unroll
    for (int d = 1; d < 16; d <<= 1) {
        #pragma unroll
        for (int i = 0; i < 8; i++) {
            s[i]  += __shfl_xor_sync(0xffffffffu, s[i],  d);
            s2[i] += __shfl_xor_sync(0xffffffffu, s2[i], d);
        }
    }
    if (tp == 0) {
        #pragma unroll
        for (int i = 0; i < 8; i++)
            part[(size_t)(o0 + i) * NT + tile] = make_float2(s[i], s2[i]);
    }
}

// ---------------------------------------------------------------------------
// GEMM1: fused gather, SIMT 128x128 (unchanged from R3)
// ---------------------------------------------------------------------------
__global__ __launch_bounds__(256, 2) void k_gemm1(const float* __restrict__ xyz,
                                                  const float* __restrict__ bias) {
    __shared__ float ws[16][128];
    __shared__ float xs[16][128];
    __shared__ int   s_n[128];
    __shared__ float s_q[128][3];

    const int p0 = blockIdx.x * 128;
    const int t  = threadIdx.x;
    const int to = t >> 4, tp = t & 15;
    const int b  = p0 / (MM * KK);

    if (t < 128) {
        int p = p0 + t;
        s_n[t] = g_idx[p];
        int q = p / KK;
        s_q[t][0] = g_newxyz[q*3+0];
        s_q[t][1] = g_newxyz[q*3+1];
        s_q[t][2] = g_newxyz[q*3+2];
    }
    __syncthreads();

    float acc[8][8];
    #pragma unroll
    for (int i = 0; i < 8; i++)
        #pragma unroll
        for (int j = 0; j < 8; j++) acc[i][j] = 0.f;

    {
        if (t < 96) {
            int ci = t >> 5, o = (t & 31) * 4;
            *(float4*)&ws[ci][o] = *(const float4*)&g_w1t[ci*O1 + o];
        }
        if (t < 128) {
            int n = s_n[t];
            const float* px = xyz + ((size_t)b * NN + n) * 3;
            xs[0][t] = px[0] - s_q[t][0];
            xs[1][t] = px[1] - s_q[t][1];
            xs[2][t] = px[2] - s_q[t][2];
        }
        __syncthreads();
        #pragma unroll
        for (int ci = 0; ci < 3; ci++) {
            float4 w0 = *(float4*)&ws[ci][to*8];
            float4 w1 = *(float4*)&ws[ci][to*8+4];
            float4 x0 = *(float4*)&xs[ci][tp*8];
            float4 x1 = *(float4*)&xs[ci][tp*8+4];
            float wv[8] = {w0.x,w0.y,w0.z,w0.w,w1.x,w1.y,w1.z,w1.w};
            float xv[8] = {x0.x,x0.y,x0.z,x0.w,x1.x,x1.y,x1.z,x1.w};
            #pragma unroll
            for (int i = 0; i < 8; i++)
                #pragma unroll
                for (int j = 0; j < 8; j++)
                    acc[i][j] = fmaf(wv[i], xv[j], acc[i][j]);
        }
        __syncthreads();
    }

    for (int ch = 0; ch < 8; ch++) {
        const int c0 = 3 + ch * 16;
        #pragma unroll
        for (int i = 0; i < 2; i++) {
            int idx = t + i*256;
            int ci = idx >> 5, o = (idx & 31) * 4;
            *(float4*)&ws[ci][o] = *(const float4*)&g_w1t[(c0 + ci)*O1 + o];
        }
        {
            int p = t >> 1, cseg = (t & 1) * 8;
            int n = s_n[p];
            const float* fp = g_featT + ((size_t)b * NN + n) * CC + (c0 - 3) + cseg;
            float4 f0 = *(const float4*)fp;
            float4 f1 = *(const float4*)(fp + 4);
            xs[cseg+0][p] = f0.x; xs[cseg+1][p] = f0.y;
            xs[cseg+2][p] = f0.z; xs[cseg+3][p] = f0.w;
            xs[cseg+4][p] = f1.x; xs[cseg+5][p] = f1.y;
            xs[cseg+6][p] = f1.z; xs[cseg+7][p] = f1.w;
        }
        __syncthreads();
        #pragma unroll
        for (int ci = 0; ci < 16; ci++) {
            float4 w0 = *(float4*)&ws[ci][to*8];
            float4 w1 = *(float4*)&ws[ci][to*8+4];
            float4 x0 = *(float4*)&xs[ci][tp*8];
            float4 x1 = *(float4*)&xs[ci][tp*8+4];
            float wv[8] = {w0.x,w0.y,w0.z,w0.w,w1.x,w1.y,w1.z,w1.w};
            float xv[8] = {x0.x,x0.y,x0.z,x0.w,x1.x,x1.y,x1.z,x1.w};
            #pragma unroll
            for (int i = 0; i < 8; i++)
                #pragma unroll
                for (int j = 0; j < 8; j++)
                    acc[i][j] = fmaf(wv[i], xv[j], acc[i][j]);
        }
        __syncthreads();
    }

    const int o0 = to * 8;
    #pragma unroll
    for (int i = 0; i < 8; i++) {
        float bs = bias[o0 + i];
        #pragma unroll
        for (int j = 0; j < 8; j++) acc[i][j] += bs;
        *(float4*)&g_y1[(size_t)(o0+i)*PP + p0 + tp*8]     = *(float4*)&acc[i][0];
        *(float4*)&g_y1[(size_t)(o0+i)*PP + p0 + tp*8 + 4] = *(float4*)&acc[i][4];
    }
    epilogue_partials(acc, o0, blockIdx.x, tp, g_part1);
}

// ---------------------------------------------------------------------------
// BN finalize (stride = nparts)
// ---------------------------------------------------------------------------
__global__ __launch_bounds__(256) void k_bnfinal(const float2* __restrict__ part,
                                                 int nparts,
                                                 const float* __restrict__ gamma,
                                                 const float* __restrict__ beta,
                                                 float2* __restrict__ abo) {
    __shared__ float2 red[256];
    int o = blockIdx.x, t = threadIdx.x;
    float s = 0.f, s2 = 0.f;
    for (int i = t; i < nparts; i += 256) {
        float2 v = part[(size_t)o * nparts + i];
        s += v.x; s2 += v.y;
    }
    red[t] = make_float2(s, s2);
    __syncthreads();
    for (int st = 128; st > 0; st >>= 1) {
        if (t < st) { red[t].x += red[t+st].x; red[t].y += red[t+st].y; }
        __syncthreads();
    }
    if (t == 0) {
        float mean = red[0].x / (float)PP;
        float var  = red[0].y / (float)PP - mean * mean;
        float a = gamma[o] * rsqrtf(var + EPSV);
        abo[o] = make_float2(a, beta[o] - a * mean);
    }
}

// ---------------------------------------------------------------------------
// bf16 3-pass mma.sync GEMM (layers 2 and 3).
// CTA: 128 O x 128 P, 256 threads = 8 warps (2 o-warps x 4 p-warps).
// Warp tile 64 O x 32 P: 4 m-frags(16) x 4 n-frags(8), k-steps of 16.
// smem [row][k] bf16, row stride 40 elems (80B, ldmatrix conflict-free).
// Staging fuses BN affine + ReLU + hi/lo bf16 split.
// Epilogue: bias; (mid) store y2[o][p] + BN partials; (last) BN partials
// + max/min over each 32-point group (no y3 materialization).
// ---------------------------------------------------------------------------
#define RS 40   // smem row stride in bf16 elems

__device__ __forceinline__ void ldsm4(uint32_t* r, uint32_t addr) {
    asm volatile("ldmatrix.sync.aligned.m8n8.x4.shared.b16 {%0,%1,%2,%3}, [%4];"
                 : "=r"(r[0]), "=r"(r[1]), "=r"(r[2]), "=r"(r[3]) : "r"(addr));
}
__device__ __forceinline__ void mma16816(float* d, const uint32_t* a, const uint32_t* b) {
    asm volatile(
        "mma.sync.aligned.m16n8k16.row.col.f32.bf16.bf16.f32 "
        "{%0,%1,%2,%3}, {%4,%5,%6,%7}, {%8,%9}, {%0,%1,%2,%3};"
        : "+f"(d[0]), "+f"(d[1]), "+f"(d[2]), "+f"(d[3])
        : "r"(a[0]), "r"(a[1]), "r"(a[2]), "r"(a[3]), "r"(b[0]), "r"(b[1]));
}
__device__ __forceinline__ void split2_store(float v0, float v1,
                                             __nv_bfloat16* hi, __nv_bfloat16* lo) {
    __nv_bfloat16 h0 = __float2bfloat16(v0);
    __nv_bfloat16 h1 = __float2bfloat16(v1);
    __nv_bfloat16 l0 = __float2bfloat16(v0 - __bfloat162float(h0));
    __nv_bfloat16 l1 = __float2bfloat16(v1 - __bfloat162float(h1));
    __nv_bfloat162 hh; hh.x = h0; hh.y = h1;
    __nv_bfloat162 ll; ll.x = l0; ll.y = l1;
    *(__nv_bfloat162*)hi = hh;
    *(__nv_bfloat162*)lo = ll;
}

template<bool LAST>
__global__ __launch_bounds__(256, 1) void k_gemm_mma(
    const float* __restrict__ yin, const float2* __restrict__ ab,
    const float* __restrict__ W, const float* __restrict__ bias,
    float* __restrict__ yout, float2* __restrict__ part)
{
    __shared__ __nv_bfloat16 sAh[128*RS];
    __shared__ __nv_bfloat16 sAl[128*RS];
    __shared__ __nv_bfloat16 sBh[128*RS];
    __shared__ __nv_bfloat16 sBl[128*RS];

    const int t    = threadIdx.x;
    const int p0   = blockIdx.x * 128;
    const int oOff = blockIdx.y * 128;
    const int ro = t >> 1, colbase = (t & 1) * 16;
    const int l = t & 31, warp = t >> 5;
    const int wo = warp >> 2, wp = warp & 3;

    const uint32_t uAh = smem_u32(sAh), uAl = smem_u32(sAl);
    const uint32_t uBh = smem_u32(sBh), uBl = smem_u32(sBl);
    // ldmatrix lane addresses (byte offsets within tile)
    const uint32_t aoffs = (uint32_t)((wo*64 + (l & 15)) * (RS*2) + (l >> 4) * 16);
    const uint32_t boffs = (uint32_t)((wp*32 + ((l >> 4) & 1)*8 + (l & 7)) * (RS*2)
                                      + ((l >> 3) & 1) * 16);

    float wreg[16], areg[16];
    // prologue: chunk 0
    {
        #pragma unroll
        for (int i = 0; i < 4; i++)
            *(float4*)&wreg[i*4] = *(const float4*)&W[(size_t)(oOff+ro)*CC + colbase + i*4];
        #pragma unroll
        for (int e = 0; e < 16; e++) {
            int c = colbase + e;
            float2 s = ab[c];
            float v = yin[(size_t)c * PP + p0 + ro];
            areg[e] = fmaxf(fmaf(v, s.x, s.y), 0.f);
        }
    }

    float acc[4][4][4];
    #pragma unroll
    for (int mi = 0; mi < 4; mi++)
        #pragma unroll
        for (int nf = 0; nf < 4; nf++)
            #pragma unroll
            for (int j = 0; j < 4; j++) acc[mi][nf][j] = 0.f;

    for (int ch = 0; ch < 4; ch++) {
        // store staged regs -> smem (hi/lo bf16)
        #pragma unroll
        for (int i = 0; i < 8; i++) {
            int e = i * 2;
            int off = ro * RS + colbase + e;
            split2_store(wreg[e], wreg[e+1], &sAh[off], &sAl[off]);
            split2_store(areg[e], areg[e+1], &sBh[off], &sBl[off]);
        }
        __syncthreads();
        if (ch < 3) {
            int c0 = (ch + 1) * 32;
            #pragma unroll
            for (int i = 0; i < 4; i++)
                *(float4*)&wreg[i*4] =
                    *(const float4*)&W[(size_t)(oOff+ro)*CC + c0 + colbase + i*4];
            #pragma unroll
            for (int e = 0; e < 16; e++) {
                int c = c0 + colbase + e;
                float2 s = ab[c];
                float v = yin[(size_t)c * PP + p0 + ro];
                areg[e] = fmaxf(fmaf(v, s.x, s.y), 0.f);
            }
        }
        #pragma unroll
        for (int ks = 0; ks < 2; ks++) {
            uint32_t ah[4][4], al[4][4];
            #pragma unroll
            for (int mi = 0; mi < 4; mi++) {
                uint32_t d = aoffs + mi * 16 * (RS*2) + ks * 32;
                ldsm4(ah[mi], uAh + d);
                ldsm4(al[mi], uAl + d);
            }
            uint32_t bh[4][2], bl[4][2];
            #pragma unroll
            for (int g = 0; g < 2; g++) {
                uint32_t d = boffs + g * 16 * (RS*2) + ks * 32;
                uint32_t r[4];
                ldsm4(r, uBh + d);
                bh[g*2][0] = r[0]; bh[g*2][1] = r[1];
                bh[g*2+1][0] = r[2]; bh[g*2+1][1] = r[3];
                ldsm4(r, uBl + d);
                bl[g*2][0] = r[0]; bl[g*2][1] = r[1];
                bl[g*2+1][0] = r[2]; bl[g*2+1][1] = r[3];
            }
            #pragma unroll
            for (int mi = 0; mi < 4; mi++)
                #pragma unroll
                for (int nf = 0; nf < 4; nf++) {
                    mma16816(acc[mi][nf], ah[mi], bh[nf]);
                    mma16816(acc[mi][nf], ah[mi], bl[nf]);
                    mma16816(acc[mi][nf], al[mi], bh[nf]);
                }
        }
        __syncthreads();
    }

    // ---- epilogue ----
    const int r = l >> 2, q = l & 3;
    const int tile4 = blockIdx.x * 4 + wp;
    #pragma unroll
    for (int mi = 0; mi < 4; mi++) {
        int o_a = oOff + wo*64 + mi*16 + r;
        int o_b = o_a + 8;
        float bsa = bias[o_a], bsb = bias[o_b];
        float sa = 0.f, sa2 = 0.f, sb = 0.f, sb2 = 0.f;
        float mxa = -INFINITY, mna = INFINITY, mxb = -INFINITY, mnb = INFINITY;
        #pragma unroll
        for (int nf = 0; nf < 4; nf++) {
            float v0 = acc[mi][nf][0] + bsa;
            float v1 = acc[mi][nf][1] + bsa;
            float v2 = acc[mi][nf][2] + bsb;
            float v3 = acc[mi][nf][3] + bsb;
            int p = p0 + wp*32 + nf*8 + q*2;
            if (!LAST) {
                *(float2*)&yout[(size_t)o_a * PP + p] = make_float2(v0, v1);
                *(float2*)&yout[(size_t)o_b * PP + p] = make_float2(v2, v3);
            }
            sa += v0 + v1; sa2 += v0*v0 + v1*v1;
            sb += v2 + v3; sb2 += v2*v2 + v3*v3;
            if (LAST) {
                mxa = fmaxf(mxa, fmaxf(v0, v1)); mna = fminf(mna, fminf(v0, v1));
                mxb = fmaxf(mxb, fmaxf(v2, v3)); mnb = fminf(mnb, fminf(v2, v3));
            }
        }
        #pragma unroll
        for (int d = 1; d < 4; d <<= 1) {
            sa  += __shfl_xor_sync(0xffffffffu, sa,  d);
            sa2 += __shfl_xor_sync(0xffffffffu, sa2, d);
            sb  += __shfl_xor_sync(0xffffffffu, sb,  d);
            sb2 += __shfl_xor_sync(0xffffffffu, sb2, d);
            if (LAST) {
                mxa = fmaxf(mxa, __shfl_xor_sync(0xffffffffu, mxa, d));
                mna = fminf(mna, __shfl_xor_sync(0xffffffffu, mna, d));
                mxb = fmaxf(mxb, __shfl_xor_sync(0xffffffffu, mxb, d));
                mnb = fminf(mnb, __shfl_xor_sync(0xffffffffu, mnb, d));
            }
        }
        if (q == 0) {
            part[(size_t)o_a * NT4 + tile4] = make_float2(sa, sa2);
            part[(size_t)o_b * NT4 + tile4] = make_float2(sb, sb2);
            if (LAST) {
                int gm = blockIdx.x * 4 + wp;  // 32-point group index
                g_mx[(size_t)gm * O3 + o_a] = mxa;
                g_mn[(size_t)gm * O3 + o_a] = mna;
                g_mx[(size_t)gm * O3 + o_b] = mxb;
                g_mn[(size_t)gm * O3 + o_b] = mnb;
            }
        }
    }
}

// ---------------------------------------------------------------------------
// Finalize: relu(a*ext + b), ext = max/min by sign(a)
// ---------------------------------------------------------------------------
__global__ void k_finalize(float* __restrict__ out) {
    __shared__ float tile[32][33];
    int gm0 = blockIdx.x * 32;
    int o0  = blockIdx.y * 32;
    int tx = threadIdx.x, ty = threadIdx.y;
    #pragma unroll
    for (int j = 0; j < 32; j += 8) {
        int gm = gm0 + ty + j;
        int o  = o0 + tx;
        float2 s = g_ab3[o];
        float ext = (s.x >= 0.f) ? g_mx[(size_t)gm * O3 + o]
                                 : g_mn[(size_t)gm * O3 + o];
        tile[tx][ty + j] = fmaxf(fmaf(ext, s.x, s.y), 0.f);
    }
    __syncthreads();
    int b = gm0 / MM;
    int m0 = gm0 - b * MM;
    #pragma unroll
    for (int j = 0; j < 32; j += 8) {
        int o = o0 + ty + j;
        out[(size_t)BB*MM*3 + ((size_t)(b * O3 + o)) * MM + m0 + tx] = tile[ty + j][tx];
    }
}

// ---------------------------------------------------------------------------
extern "C" void kernel_launch(void* const* d_in, const int* in_sizes, int n_in,
                              void* d_out, int out_size) {
    const float* xyz     = (const float*)d_in[0];
    const float* feat    = (const float*)d_in[1];
    const int*   indices = (const int*)d_in[2];
    const float* w1 = (const float*)d_in[3];
    const float* b1 = (const float*)d_in[4];
    const float* g1 = (const float*)d_in[5];
    const float* be1 = (const float*)d_in[6];
    const float* w2 = (const float*)d_in[7];
    const float* b2 = (const float*)d_in[8];
    const float* g2 = (const float*)d_in[9];
    const float* be2 = (const float*)d_in[10];
    const float* w3 = (const float*)d_in[11];
    const float* b3 = (const float*)d_in[12];
    const float* g3 = (const float*)d_in[13];
    const float* be3 = (const float*)d_in[14];
    float* out = (float*)d_out;

    float* w1t; cudaGetSymbolAddress((void**)&w1t, g_w1t);
    float* y1; cudaGetSymbolAddress((void**)&y1, g_y1);
    float* y2; cudaGetSymbolAddress((void**)&y2, g_y2);
    float2* ab1; cudaGetSymbolAddress((void**)&ab1, g_ab1);
    float2* ab2; cudaGetSymbolAddress((void**)&ab2, g_ab2);
    float2* ab3; cudaGetSymbolAddress((void**)&ab3, g_ab3);
    float2* part1; cudaGetSymbolAddress((void**)&part1, g_part1);
    float2* part2; cudaGetSymbolAddress((void**)&part2, g_part2);
    float2* part3; cudaGetSymbolAddress((void**)&part3, g_part3);

    k_gather_newxyz<<<(BB*MM + 255) / 256, 256>>>(xyz, indices, out);
    k_transpose_feat<<<dim3(NN/32, CC/32, BB), dim3(32, 8)>>>(feat);
    k_wtrans<<<(O1*C1 + 255)/256, 256>>>(w1, w1t, O1, C1);
    k_ballquery<<<(BB*MM) / 8, 256>>>(xyz);
    k_gemm1<<<PP/128, 256>>>(xyz, b1);
    k_bnfinal<<<O1, 256>>>(part1, NT, g1, be1, ab1);
    k_gemm_mma<false><<<dim3(PP/128, 1), 256>>>(y1, ab1, w2, b2, y2, part2);
    k_bnfinal<<<O2, 256>>>(part2, NT4, g2, be2, ab2);
    k_gemm_mma<true><<<dim3(PP/128, 2), 256>>>(y2, ab2, w3, b3, nullptr, part3);
    k_bnfinal<<<O3, 256>>>(part3, NT4, g3, be3, ab3);
    k_finalize<<<dim3(BB*MM/32, O3/32), dim3(32, 8)>>>(out);
}

// round 5
// speedup vs baseline: 2.0697x; 1.1540x over previous
#include <cuda_runtime.h>
#include <cuda_bf16.h>
#include <cstdint>
#include <math.h>

// Problem constants
#define BB 4
#define NN 16384
#define CC 128
#define MM 1024
#define KK 32
#define PP (BB*MM*KK)     // 131072 points
#define C1 131
#define O1 128
#define O2 128
#define O3 256
#define RAD2 0.16f
#define EPSV 1e-5f
#define NT (PP/128)       // 1024 p-tiles of 128 (gemm1 partials)
#define NT4 (PP/32)       // 4096 per-warp partial slots (mma gemms)

// ---------------------------------------------------------------------------
// Scratch
// ---------------------------------------------------------------------------
__device__ float  g_featT[(size_t)BB*NN*CC];
__device__ float  g_newxyz[BB*MM*3];
__device__ int    g_idx[BB*MM*KK];
__device__ float  g_y1[(size_t)O1*PP];
__device__ float  g_y2[(size_t)O2*PP];
__device__ float  g_w1t[C1*O1];
__device__ float2 g_ab1[O1];
__device__ float2 g_ab2[O2];
__device__ float2 g_ab3[O3];
__device__ float2 g_part1[O1*NT];
__device__ float2 g_part2[(size_t)O2*NT4];
__device__ float2 g_part3[(size_t)O3*NT4];
__device__ float  g_mx[(size_t)BB*MM*O3];
__device__ float  g_mn[(size_t)BB*MM*O3];

__device__ __forceinline__ uint32_t smem_u32(const void* p) {
    uint32_t a;
    asm("{ .reg .u64 tmp; cvta.to.shared.u64 tmp, %1; cvt.u32.u64 %0, tmp; }"
        : "=r"(a) : "l"(p));
    return a;
}

// ---------------------------------------------------------------------------
// K0: gather new_xyz
// ---------------------------------------------------------------------------
__global__ void k_gather_newxyz(const float* __restrict__ xyz,
                                const int* __restrict__ indices,
                                float* __restrict__ out) {
    int i = blockIdx.x * blockDim.x + threadIdx.x;
    if (i >= BB * MM) return;
    int b = i / MM;
    int n = indices[i];
    const float* src = xyz + ((size_t)b * NN + n) * 3;
    float x = src[0], y = src[1], z = src[2];
    g_newxyz[i*3+0] = x; g_newxyz[i*3+1] = y; g_newxyz[i*3+2] = z;
    out[i*3+0] = x; out[i*3+1] = y; out[i*3+2] = z;
}

// ---------------------------------------------------------------------------
// K1: transpose features (B,C,N) -> (B,N,C)
// ---------------------------------------------------------------------------
__global__ void k_transpose_feat(const float* __restrict__ f) {
    __shared__ float t[32][33];
    int b  = blockIdx.z;
    int c0 = blockIdx.y * 32;
    int n0 = blockIdx.x * 32;
    int tx = threadIdx.x, ty = threadIdx.y;
    #pragma unroll
    for (int j = 0; j < 32; j += 8)
        t[ty + j][tx] = f[((size_t)b * CC + c0 + ty + j) * NN + n0 + tx];
    __syncthreads();
    #pragma unroll
    for (int j = 0; j < 32; j += 8)
        g_featT[((size_t)b * NN + n0 + ty + j) * CC + c0 + tx] = t[tx][ty + j];
}

// K1b: transpose W1 (O,C)->(C,O)
__global__ void k_wtrans(const float* __restrict__ w, float* __restrict__ wt,
                         int O, int Cn) {
    int i = blockIdx.x * 256 + threadIdx.x;
    if (i < O * Cn) {
        int o = i / Cn, c = i % Cn;
        wt[c * O + o] = w[i];
    }
}

// ---------------------------------------------------------------------------
// K2: ball query — BLOCK per query, 512 threads.
// First K within-radius points in index order; pad with first found.
// Per-iteration: 512 candidates, per-warp ballot + 16-warp prefix (smem),
// double-buffered warp counts -> single __syncthreads per iteration.
// ---------------------------------------------------------------------------
__global__ __launch_bounds__(512) void k_ballquery(const float* __restrict__ xyz) {
    __shared__ int s_found[KK];
    __shared__ int s_wcnt[2][16];
    const int q = blockIdx.x;
    const int b = q / MM;
    const int t = threadIdx.x, l = t & 31, w = t >> 5;
    const float qx = g_newxyz[q*3+0], qy = g_newxyz[q*3+1], qz = g_newxyz[q*3+2];
    const float* base = xyz + (size_t)b * NN * 3;
    int cnt = 0;
    int parity = 0;
    for (int n0 = 0; n0 < NN; n0 += 512, parity ^= 1) {
        int n = n0 + t;
        float dx = base[n*3+0] - qx;
        float dy = base[n*3+1] - qy;
        float dz = base[n*3+2] - qz;
        bool within = (dx*dx + dy*dy + dz*dz) < RAD2;
        unsigned bal = __ballot_sync(0xffffffffu, within);
        if (l == 0) s_wcnt[parity][w] = __popc(bal);
        __syncthreads();
        int off = cnt, tot = 0;
        #pragma unroll
        for (int i = 0; i < 16; i++) {
            int c = s_wcnt[parity][i];
            if (i < w) off += c;
            tot += c;
        }
        if (within) {
            int r = off + __popc(bal & ((1u << l) - 1u));
            if (r < KK) s_found[r] = n;
        }
        cnt += tot;               // identical in every thread -> uniform break
        if (cnt >= KK) break;
    }
    __syncthreads();
    if (t < KK) {
        int pad = (cnt > 0) ? s_found[0] : 0;
        g_idx[q * KK + t] = (t < cnt) ? s_found[t] : pad;
    }
}

// ---------------------------------------------------------------------------
// gemm1 partials helper
// ---------------------------------------------------------------------------
__device__ __forceinline__ void epilogue_partials(float v[8][8], int o0,
                                                  int tile, int tp,
                                                  float2* __restrict__ part) {
    float s[8], s2[8];
    #pragma unroll
    for (int i = 0; i < 8; i++) {
        float a = 0.f, a2 = 0.f;
        #pragma unroll
        for (int j = 0; j < 8; j++) { a += v[i][j]; a2 += v[i][j]*v[i][j]; }
        s[i] = a; s2[i] = a2;
    }
    #pragma unroll
    for (int d = 1; d < 16; d <<= 1) {
        #pragma unroll
        for (int i = 0; i < 8; i++) {
            s[i]  += __shfl_xor_sync(0xffffffffu, s[i],  d);
            s2[i] += __shfl_xor_sync(0xffffffffu, s2[i], d);
        }
    }
    if (tp == 0) {
        #pragma unroll
        for (int i = 0; i < 8; i++)
            part[(size_t)(o0 + i) * NT + tile] = make_float2(s[i], s2[i]);
    }
}

// ---------------------------------------------------------------------------
// GEMM1: fused gather, SIMT 128x128
// ---------------------------------------------------------------------------
__global__ __launch_bounds__(256, 2) void k_gemm1(const float* __restrict__ xyz,
                                                  const float* __restrict__ bias) {
    __shared__ float ws[16][128];
    __shared__ float xs[16][128];
    __shared__ int   s_n[128];
    __shared__ float s_q[128][3];

    const int p0 = blockIdx.x * 128;
    const int t  = threadIdx.x;
    const int to = t >> 4, tp = t & 15;
    const int b  = p0 / (MM * KK);

    if (t < 128) {
        int p = p0 + t;
        s_n[t] = g_idx[p];
        int q = p / KK;
        s_q[t][0] = g_newxyz[q*3+0];
        s_q[t][1] = g_newxyz[q*3+1];
        s_q[t][2] = g_newxyz[q*3+2];
    }
    __syncthreads();

    float acc[8][8];
    #pragma unroll
    for (int i = 0; i < 8; i++)
        #pragma unroll
        for (int j = 0; j < 8; j++) acc[i][j] = 0.f;

    {
        if (t < 96) {
            int ci = t >> 5, o = (t & 31) * 4;
            *(float4*)&ws[ci][o] = *(const float4*)&g_w1t[ci*O1 + o];
        }
        if (t < 128) {
            int n = s_n[t];
            const float* px = xyz + ((size_t)b * NN + n) * 3;
            xs[0][t] = px[0] - s_q[t][0];
            xs[1][t] = px[1] - s_q[t][1];
            xs[2][t] = px[2] - s_q[t][2];
        }
        __syncthreads();
        #pragma unroll
        for (int ci = 0; ci < 3; ci++) {
            float4 w0 = *(float4*)&ws[ci][to*8];
            float4 w1 = *(float4*)&ws[ci][to*8+4];
            float4 x0 = *(float4*)&xs[ci][tp*8];
            float4 x1 = *(float4*)&xs[ci][tp*8+4];
            float wv[8] = {w0.x,w0.y,w0.z,w0.w,w1.x,w1.y,w1.z,w1.w};
            float xv[8] = {x0.x,x0.y,x0.z,x0.w,x1.x,x1.y,x1.z,x1.w};
            #pragma unroll
            for (int i = 0; i < 8; i++)
                #pragma unroll
                for (int j = 0; j < 8; j++)
                    acc[i][j] = fmaf(wv[i], xv[j], acc[i][j]);
        }
        __syncthreads();
    }

    for (int ch = 0; ch < 8; ch++) {
        const int c0 = 3 + ch * 16;
        #pragma unroll
        for (int i = 0; i < 2; i++) {
            int idx = t + i*256;
            int ci = idx >> 5, o = (idx & 31) * 4;
            *(float4*)&ws[ci][o] = *(const float4*)&g_w1t[(c0 + ci)*O1 + o];
        }
        {
            int p = t >> 1, cseg = (t & 1) * 8;
            int n = s_n[p];
            const float* fp = g_featT + ((size_t)b * NN + n) * CC + (c0 - 3) + cseg;
            float4 f0 = *(const float4*)fp;
            float4 f1 = *(const float4*)(fp + 4);
            xs[cseg+0][p] = f0.x; xs[cseg+1][p] = f0.y;
            xs[cseg+2][p] = f0.z; xs[cseg+3][p] = f0.w;
            xs[cseg+4][p] = f1.x; xs[cseg+5][p] = f1.y;
            xs[cseg+6][p] = f1.z; xs[cseg+7][p] = f1.w;
        }
        __syncthreads();
        #pragma unroll
        for (int ci = 0; ci < 16; ci++) {
            float4 w0 = *(float4*)&ws[ci][to*8];
            float4 w1 = *(float4*)&ws[ci][to*8+4];
            float4 x0 = *(float4*)&xs[ci][tp*8];
            float4 x1 = *(float4*)&xs[ci][tp*8+4];
            float wv[8] = {w0.x,w0.y,w0.z,w0.w,w1.x,w1.y,w1.z,w1.w};
            float xv[8] = {x0.x,x0.y,x0.z,x0.w,x1.x,x1.y,x1.z,x1.w};
            #pragma unroll
            for (int i = 0; i < 8; i++)
                #pragma unroll
                for (int j = 0; j < 8; j++)
                    acc[i][j] = fmaf(wv[i], xv[j], acc[i][j]);
        }
        __syncthreads();
    }

    const int o0 = to * 8;
    #pragma unroll
    for (int i = 0; i < 8; i++) {
        float bs = bias[o0 + i];
        #pragma unroll
        for (int j = 0; j < 8; j++) acc[i][j] += bs;
        *(float4*)&g_y1[(size_t)(o0+i)*PP + p0 + tp*8]     = *(float4*)&acc[i][0];
        *(float4*)&g_y1[(size_t)(o0+i)*PP + p0 + tp*8 + 4] = *(float4*)&acc[i][4];
    }
    epilogue_partials(acc, o0, blockIdx.x, tp, g_part1);
}

// ---------------------------------------------------------------------------
// BN finalize
// ---------------------------------------------------------------------------
__global__ __launch_bounds__(256) void k_bnfinal(const float2* __restrict__ part,
                                                 int nparts,
                                                 const float* __restrict__ gamma,
                                                 const float* __restrict__ beta,
                                                 float2* __restrict__ abo) {
    __shared__ float2 red[256];
    int o = blockIdx.x, t = threadIdx.x;
    float s = 0.f, s2 = 0.f;
    for (int i = t; i < nparts; i += 256) {
        float2 v = part[(size_t)o * nparts + i];
        s += v.x; s2 += v.y;
    }
    red[t] = make_float2(s, s2);
    __syncthreads();
    for (int st = 128; st > 0; st >>= 1) {
        if (t < st) { red[t].x += red[t+st].x; red[t].y += red[t+st].y; }
        __syncthreads();
    }
    if (t == 0) {
        float mean = red[0].x / (float)PP;
        float var  = red[0].y / (float)PP - mean * mean;
        float a = gamma[o] * rsqrtf(var + EPSV);
        abo[o] = make_float2(a, beta[o] - a * mean);
    }
}

// ---------------------------------------------------------------------------
// bf16 3-pass mma.sync GEMM (layers 2 and 3)
// ---------------------------------------------------------------------------
#define RS 40   // smem row stride in bf16 elems

__device__ __forceinline__ void ldsm4(uint32_t* r, uint32_t addr) {
    asm volatile("ldmatrix.sync.aligned.m8n8.x4.shared.b16 {%0,%1,%2,%3}, [%4];"
                 : "=r"(r[0]), "=r"(r[1]), "=r"(r[2]), "=r"(r[3]) : "r"(addr));
}
__device__ __forceinline__ void mma16816(float* d, const uint32_t* a, const uint32_t* b) {
    asm volatile(
        "mma.sync.aligned.m16n8k16.row.col.f32.bf16.bf16.f32 "
        "{%0,%1,%2,%3}, {%4,%5,%6,%7}, {%8,%9}, {%0,%1,%2,%3};"
        : "+f"(d[0]), "+f"(d[1]), "+f"(d[2]), "+f"(d[3])
        : "r"(a[0]), "r"(a[1]), "r"(a[2]), "r"(a[3]), "r"(b[0]), "r"(b[1]));
}
__device__ __forceinline__ void split2_store(float v0, float v1,
                                             __nv_bfloat16* hi, __nv_bfloat16* lo) {
    __nv_bfloat16 h0 = __float2bfloat16(v0);
    __nv_bfloat16 h1 = __float2bfloat16(v1);
    __nv_bfloat16 l0 = __float2bfloat16(v0 - __bfloat162float(h0));
    __nv_bfloat16 l1 = __float2bfloat16(v1 - __bfloat162float(h1));
    __nv_bfloat162 hh; hh.x = h0; hh.y = h1;
    __nv_bfloat162 ll; ll.x = l0; ll.y = l1;
    *(__nv_bfloat162*)hi = hh;
    *(__nv_bfloat162*)lo = ll;
}

template<bool LAST>
__global__ __launch_bounds__(256, 1) void k_gemm_mma(
    const float* __restrict__ yin, const float2* __restrict__ ab,
    const float* __restrict__ W, const float* __restrict__ bias,
    float* __restrict__ yout, float2* __restrict__ part)
{
    __shared__ __nv_bfloat16 sAh[128*RS];
    __shared__ __nv_bfloat16 sAl[128*RS];
    __shared__ __nv_bfloat16 sBh[128*RS];
    __shared__ __nv_bfloat16 sBl[128*RS];

    const int t    = threadIdx.x;
    const int p0   = blockIdx.x * 128;
    const int oOff = blockIdx.y * 128;
    const int ro = t >> 1, colbase = (t & 1) * 16;
    const int l = t & 31, warp = t >> 5;
    const int wo = warp >> 2, wp = warp & 3;

    const uint32_t uAh = smem_u32(sAh), uAl = smem_u32(sAl);
    const uint32_t uBh = smem_u32(sBh), uBl = smem_u32(sBl);
    const uint32_t aoffs = (uint32_t)((wo*64 + (l & 15)) * (RS*2) + (l >> 4) * 16);
    const uint32_t boffs = (uint32_t)((wp*32 + ((l >> 4) & 1)*8 + (l & 7)) * (RS*2)
                                      + ((l >> 3) & 1) * 16);

    float wreg[16], areg[16];
    {
        #pragma unroll
        for (int i = 0; i < 4; i++)
            *(float4*)&wreg[i*4] = *(const float4*)&W[(size_t)(oOff+ro)*CC + colbase + i*4];
        #pragma unroll
        for (int e = 0; e < 16; e++) {
            int c = colbase + e;
            float2 s = ab[c];
            float v = yin[(size_t)c * PP + p0 + ro];
            areg[e] = fmaxf(fmaf(v, s.x, s.y), 0.f);
        }
    }

    float acc[4][4][4];
    #pragma unroll
    for (int mi = 0; mi < 4; mi++)
        #pragma unroll
        for (int nf = 0; nf < 4; nf++)
            #pragma unroll
            for (int j = 0; j < 4; j++) acc[mi][nf][j] = 0.f;

    for (int ch = 0; ch < 4; ch++) {
        #pragma unroll
        for (int i = 0; i < 8; i++) {
            int e = i * 2;
            int off = ro * RS + colbase + e;
            split2_store(wreg[e], wreg[e+1], &sAh[off], &sAl[off]);
            split2_store(areg[e], areg[e+1], &sBh[off], &sBl[off]);
        }
        __syncthreads();
        if (ch < 3) {
            int c0 = (ch + 1) * 32;
            #pragma unroll
            for (int i = 0; i < 4; i++)
                *(float4*)&wreg[i*4] =
                    *(const float4*)&W[(size_t)(oOff+ro)*CC + c0 + colbase + i*4];
            #pragma unroll
            for (int e = 0; e < 16; e++) {
                int c = c0 + colbase + e;
                float2 s = ab[c];
                float v = yin[(size_t)c * PP + p0 + ro];
                areg[e] = fmaxf(fmaf(v, s.x, s.y), 0.f);
            }
        }
        #pragma unroll
        for (int ks = 0; ks < 2; ks++) {
            uint32_t ah[4][4], al[4][4];
            #pragma unroll
            for (int mi = 0; mi < 4; mi++) {
                uint32_t d = aoffs + mi * 16 * (RS*2) + ks * 32;
                ldsm4(ah[mi], uAh + d);
                ldsm4(al[mi], uAl + d);
            }
            uint32_t bh[4][2], bl[4][2];
            #pragma unroll
            for (int g = 0; g < 2; g++) {
                uint32_t d = boffs + g * 16 * (RS*2) + ks * 32;
                uint32_t r[4];
                ldsm4(r, uBh + d);
                bh[g*2][0] = r[0]; bh[g*2][1] = r[1];
                bh[g*2+1][0] = r[2]; bh[g*2+1][1] = r[3];
                ldsm4(r, uBl + d);
                bl[g*2][0] = r[0]; bl[g*2][1] = r[1];
                bl[g*2+1][0] = r[2]; bl[g*2+1][1] = r[3];
            }
            #pragma unroll
            for (int mi = 0; mi < 4; mi++)
                #pragma unroll
                for (int nf = 0; nf < 4; nf++) {
                    mma16816(acc[mi][nf], ah[mi], bh[nf]);
                    mma16816(acc[mi][nf], ah[mi], bl[nf]);
                    mma16816(acc[mi][nf], al[mi], bh[nf]);
                }
        }
        __syncthreads();
    }

    const int r = l >> 2, q = l & 3;
    const int tile4 = blockIdx.x * 4 + wp;
    #pragma unroll
    for (int mi = 0; mi < 4; mi++) {
        int o_a = oOff + wo*64 + mi*16 + r;
        int o_b = o_a + 8;
        float bsa = bias[o_a], bsb = bias[o_b];
        float sa = 0.f, sa2 = 0.f, sb = 0.f, sb2 = 0.f;
        float mxa = -INFINITY, mna = INFINITY, mxb = -INFINITY, mnb = INFINITY;
        #pragma unroll
        for (int nf = 0; nf < 4; nf++) {
            float v0 = acc[mi][nf][0] + bsa;
            float v1 = acc[mi][nf][1] + bsa;
            float v2 = acc[mi][nf][2] + bsb;
            float v3 = acc[mi][nf][3] + bsb;
            int p = p0 + wp*32 + nf*8 + q*2;
            if (!LAST) {
                *(float2*)&yout[(size_t)o_a * PP + p] = make_float2(v0, v1);
                *(float2*)&yout[(size_t)o_b * PP + p] = make_float2(v2, v3);
            }
            sa += v0 + v1; sa2 += v0*v0 + v1*v1;
            sb += v2 + v3; sb2 += v2*v2 + v3*v3;
            if (LAST) {
                mxa = fmaxf(mxa, fmaxf(v0, v1)); mna = fminf(mna, fminf(v0, v1));
                mxb = fmaxf(mxb, fmaxf(v2, v3)); mnb = fminf(mnb, fminf(v2, v3));
            }
        }
        #pragma unroll
        for (int d = 1; d < 4; d <<= 1) {
            sa  += __shfl_xor_sync(0xffffffffu, sa,  d);
            sa2 += __shfl_xor_sync(0xffffffffu, sa2, d);
            sb  += __shfl_xor_sync(0xffffffffu, sb,  d);
            sb2 += __shfl_xor_sync(0xffffffffu, sb2, d);
            if (LAST) {
                mxa = fmaxf(mxa, __shfl_xor_sync(0xffffffffu, mxa, d));
                mna = fminf(mna, __shfl_xor_sync(0xffffffffu, mna, d));
                mxb = fmaxf(mxb, __shfl_xor_sync(0xffffffffu, mxb, d));
                mnb = fminf(mnb, __shfl_xor_sync(0xffffffffu, mnb, d));
            }
        }
        if (q == 0) {
            part[(size_t)o_a * NT4 + tile4] = make_float2(sa, sa2);
            part[(size_t)o_b * NT4 + tile4] = make_float2(sb, sb2);
            if (LAST) {
                int gm = blockIdx.x * 4 + wp;
                g_mx[(size_t)gm * O3 + o_a] = mxa;
                g_mn[(size_t)gm * O3 + o_a] = mna;
                g_mx[(size_t)gm * O3 + o_b] = mxb;
                g_mn[(size_t)gm * O3 + o_b] = mnb;
            }
        }
    }
}

// ---------------------------------------------------------------------------
// Finalize: relu(a*ext + b), ext = max/min by sign(a)
// ---------------------------------------------------------------------------
__global__ void k_finalize(float* __restrict__ out) {
    __shared__ float tile[32][33];
    int gm0 = blockIdx.x * 32;
    int o0  = blockIdx.y * 32;
    int tx = threadIdx.x, ty = threadIdx.y;
    #pragma unroll
    for (int j = 0; j < 32; j += 8) {
        int gm = gm0 + ty + j;
        int o  = o0 + tx;
        float2 s = g_ab3[o];
        float ext = (s.x >= 0.f) ? g_mx[(size_t)gm * O3 + o]
                                 : g_mn[(size_t)gm * O3 + o];
        tile[tx][ty + j] = fmaxf(fmaf(ext, s.x, s.y), 0.f);
    }
    __syncthreads();
    int b = gm0 / MM;
    int m0 = gm0 - b * MM;
    #pragma unroll
    for (int j = 0; j < 32; j += 8) {
        int o = o0 + ty + j;
        out[(size_t)BB*MM*3 + ((size_t)(b * O3 + o)) * MM + m0 + tx] = tile[ty + j][tx];
    }
}

// ---------------------------------------------------------------------------
extern "C" void kernel_launch(void* const* d_in, const int* in_sizes, int n_in,
                              void* d_out, int out_size) {
    const float* xyz     = (const float*)d_in[0];
    const float* feat    = (const float*)d_in[1];
    const int*   indices = (const int*)d_in[2];
    const float* w1 = (const float*)d_in[3];
    const float* b1 = (const float*)d_in[4];
    const float* g1 = (const float*)d_in[5];
    const float* be1 = (const float*)d_in[6];
    const float* w2 = (const float*)d_in[7];
    const float* b2 = (const float*)d_in[8];
    const float* g2 = (const float*)d_in[9];
    const float* be2 = (const float*)d_in[10];
    const float* w3 = (const float*)d_in[11];
    const float* b3 = (const float*)d_in[12];
    const float* g3 = (const float*)d_in[13];
    const float* be3 = (const float*)d_in[14];
    float* out = (float*)d_out;

    float* w1t; cudaGetSymbolAddress((void**)&w1t, g_w1t);
    float* y1; cudaGetSymbolAddress((void**)&y1, g_y1);
    float* y2; cudaGetSymbolAddress((void**)&y2, g_y2);
    float2* ab1; cudaGetSymbolAddress((void**)&ab1, g_ab1);
    float2* ab2; cudaGetSymbolAddress((void**)&ab2, g_ab2);
    float2* ab3; cudaGetSymbolAddress((void**)&ab3, g_ab3);
    float2* part1; cudaGetSymbolAddress((void**)&part1, g_part1);
    float2* part2; cudaGetSymbolAddress((void**)&part2, g_part2);
    float2* part3; cudaGetSymbolAddress((void**)&part3, g_part3);

    k_gather_newxyz<<<(BB*MM + 255) / 256, 256>>>(xyz, indices, out);
    k_ballquery<<<BB*MM, 512>>>(xyz);
    k_transpose_feat<<<dim3(NN/32, CC/32, BB), dim3(32, 8)>>>(feat);
    k_wtrans<<<(O1*C1 + 255)/256, 256>>>(w1, w1t, O1, C1);
    k_gemm1<<<PP/128, 256>>>(xyz, b1);
    k_bnfinal<<<O1, 256>>>(part1, NT, g1, be1, ab1);
    k_gemm_mma<false><<<dim3(PP/128, 1), 256>>>(y1, ab1, w2, b2, y2, part2);
    k_bnfinal<<<O2, 256>>>(part2, NT4, g2, be2, ab2);
    k_gemm_mma<true><<<dim3(PP/128, 2), 256>>>(y2, ab2, w3, b3, nullptr, part3);
    k_bnfinal<<<O3, 256>>>(part3, NT4, g3, be3, ab3);
    k_finalize<<<dim3(BB*MM/32, O3/32), dim3(32, 8)>>>(out);
}

// round 6
// speedup vs baseline: 2.1981x; 1.0620x over previous
#include <cuda_runtime.h>
#include <cuda_bf16.h>
#include <cstdint>
#include <math.h>

// Problem constants
#define BB 4
#define NN 16384
#define CC 128
#define MM 1024
#define KK 32
#define PP (BB*MM*KK)     // 131072 points
#define C1 131
#define O1 128
#define O2 128
#define O3 256
#define RAD2 0.16f
#define EPSV 1e-5f
#define NT4 (PP/32)       // 4096 per-warp partial slots

// ---------------------------------------------------------------------------
// Scratch
// ---------------------------------------------------------------------------
__device__ float  g_featT[(size_t)BB*NN*CC];
__device__ float  g_newxyz[BB*MM*3];
__device__ int    g_idx[BB*MM*KK];
__device__ float  g_y1[(size_t)O1*PP];
__device__ float  g_y2[(size_t)O2*PP];
__device__ float2 g_ab1[O1];
__device__ float2 g_ab2[O2];
__device__ float2 g_ab3[O3];
__device__ float2 g_part1[(size_t)O1*NT4];
__device__ float2 g_part2[(size_t)O2*NT4];
__device__ float2 g_part3[(size_t)O3*NT4];
__device__ float  g_mx[(size_t)BB*MM*O3];
__device__ float  g_mn[(size_t)BB*MM*O3];

__device__ __forceinline__ uint32_t smem_u32(const void* p) {
    uint32_t a;
    asm("{ .reg .u64 tmp; cvta.to.shared.u64 tmp, %1; cvt.u32.u64 %0, tmp; }"
        : "=r"(a) : "l"(p));
    return a;
}

// ---------------------------------------------------------------------------
// K0: gather new_xyz
// ---------------------------------------------------------------------------
__global__ void k_gather_newxyz(const float* __restrict__ xyz,
                                const int* __restrict__ indices,
                                float* __restrict__ out) {
    int i = blockIdx.x * blockDim.x + threadIdx.x;
    if (i >= BB * MM) return;
    int b = i / MM;
    int n = indices[i];
    const float* src = xyz + ((size_t)b * NN + n) * 3;
    float x = src[0], y = src[1], z = src[2];
    g_newxyz[i*3+0] = x; g_newxyz[i*3+1] = y; g_newxyz[i*3+2] = z;
    out[i*3+0] = x; out[i*3+1] = y; out[i*3+2] = z;
}

// ---------------------------------------------------------------------------
// K1: transpose features (B,C,N) -> (B,N,C)
// ---------------------------------------------------------------------------
__global__ void k_transpose_feat(const float* __restrict__ f) {
    __shared__ float t[32][33];
    int b  = blockIdx.z;
    int c0 = blockIdx.y * 32;
    int n0 = blockIdx.x * 32;
    int tx = threadIdx.x, ty = threadIdx.y;
    #pragma unroll
    for (int j = 0; j < 32; j += 8)
        t[ty + j][tx] = f[((size_t)b * CC + c0 + ty + j) * NN + n0 + tx];
    __syncthreads();
    #pragma unroll
    for (int j = 0; j < 32; j += 8)
        g_featT[((size_t)b * NN + n0 + ty + j) * CC + c0 + tx] = t[tx][ty + j];
}

// ---------------------------------------------------------------------------
// K2: ball query — BLOCK per query, 512 threads.
// ---------------------------------------------------------------------------
__global__ __launch_bounds__(512) void k_ballquery(const float* __restrict__ xyz) {
    __shared__ int s_found[KK];
    __shared__ int s_wcnt[2][16];
    const int q = blockIdx.x;
    const int b = q / MM;
    const int t = threadIdx.x, l = t & 31, w = t >> 5;
    const float qx = g_newxyz[q*3+0], qy = g_newxyz[q*3+1], qz = g_newxyz[q*3+2];
    const float* base = xyz + (size_t)b * NN * 3;
    int cnt = 0;
    int parity = 0;
    for (int n0 = 0; n0 < NN; n0 += 512, parity ^= 1) {
        int n = n0 + t;
        float dx = base[n*3+0] - qx;
        float dy = base[n*3+1] - qy;
        float dz = base[n*3+2] - qz;
        bool within = (dx*dx + dy*dy + dz*dz) < RAD2;
        unsigned bal = __ballot_sync(0xffffffffu, within);
        if (l == 0) s_wcnt[parity][w] = __popc(bal);
        __syncthreads();
        int off = cnt, tot = 0;
        #pragma unroll
        for (int i = 0; i < 16; i++) {
            int c = s_wcnt[parity][i];
            if (i < w) off += c;
            tot += c;
        }
        if (within) {
            int r = off + __popc(bal & ((1u << l) - 1u));
            if (r < KK) s_found[r] = n;
        }
        cnt += tot;
        if (cnt >= KK) break;
    }
    __syncthreads();
    if (t < KK) {
        int pad = (cnt > 0) ? s_found[0] : 0;
        g_idx[q * KK + t] = (t < cnt) ? s_found[t] : pad;
    }
}

// ---------------------------------------------------------------------------
// BN finalize
// ---------------------------------------------------------------------------
__global__ __launch_bounds__(256) void k_bnfinal(const float2* __restrict__ part,
                                                 int nparts,
                                                 const float* __restrict__ gamma,
                                                 const float* __restrict__ beta,
                                                 float2* __restrict__ abo) {
    __shared__ float2 red[256];
    int o = blockIdx.x, t = threadIdx.x;
    float s = 0.f, s2 = 0.f;
    for (int i = t; i < nparts; i += 256) {
        float2 v = part[(size_t)o * nparts + i];
        s += v.x; s2 += v.y;
    }
    red[t] = make_float2(s, s2);
    __syncthreads();
    for (int st = 128; st > 0; st >>= 1) {
        if (t < st) { red[t].x += red[t+st].x; red[t].y += red[t+st].y; }
        __syncthreads();
    }
    if (t == 0) {
        float mean = red[0].x / (float)PP;
        float var  = red[0].y / (float)PP - mean * mean;
        float a = gamma[o] * rsqrtf(var + EPSV);
        abo[o] = make_float2(a, beta[o] - a * mean);
    }
}

// ---------------------------------------------------------------------------
// mma helpers
// ---------------------------------------------------------------------------
#define RS 40   // smem row stride in bf16 elems

__device__ __forceinline__ void ldsm4(uint32_t* r, uint32_t addr) {
    asm volatile("ldmatrix.sync.aligned.m8n8.x4.shared.b16 {%0,%1,%2,%3}, [%4];"
                 : "=r"(r[0]), "=r"(r[1]), "=r"(r[2]), "=r"(r[3]) : "r"(addr));
}
__device__ __forceinline__ void mma16816(float* d, const uint32_t* a, const uint32_t* b) {
    asm volatile(
        "mma.sync.aligned.m16n8k16.row.col.f32.bf16.bf16.f32 "
        "{%0,%1,%2,%3}, {%4,%5,%6,%7}, {%8,%9}, {%0,%1,%2,%3};"
        : "+f"(d[0]), "+f"(d[1]), "+f"(d[2]), "+f"(d[3])
        : "r"(a[0]), "r"(a[1]), "r"(a[2]), "r"(a[3]), "r"(b[0]), "r"(b[1]));
}
__device__ __forceinline__ void split2_store(float v0, float v1,
                                             __nv_bfloat16* hi, __nv_bfloat16* lo) {
    __nv_bfloat16 h0 = __float2bfloat16(v0);
    __nv_bfloat16 h1 = __float2bfloat16(v1);
    __nv_bfloat16 l0 = __float2bfloat16(v0 - __bfloat162float(h0));
    __nv_bfloat16 l1 = __float2bfloat16(v1 - __bfloat162float(h1));
    __nv_bfloat162 hh; hh.x = h0; hh.y = h1;
    __nv_bfloat162 ll; ll.x = l0; ll.y = l1;
    *(__nv_bfloat162*)hi = hh;
    *(__nv_bfloat162*)lo = ll;
}

// ---------------------------------------------------------------------------
// GEMM1 via mma: 128 feat channels through bf16 3-pass mma,
// + exact fp32 rank-3 update for the xyz-diff channels.
// CTA 128 O x 128 P, 256 threads, layout identical to k_gemm_mma.
// ---------------------------------------------------------------------------
__global__ __launch_bounds__(256, 1) void k_gemm1_mma(
    const float* __restrict__ xyz, const float* __restrict__ W,   // W = w1 (O1 x C1)
    const float* __restrict__ bias)
{
    __shared__ __nv_bfloat16 sAh[128*RS];
    __shared__ __nv_bfloat16 sAl[128*RS];
    __shared__ __nv_bfloat16 sBh[128*RS];
    __shared__ __nv_bfloat16 sBl[128*RS];
    __shared__ int   s_n[128];
    __shared__ float s_xyzd[3][128];
    __shared__ float s_wxyz[3][128];

    const int t  = threadIdx.x;
    const int p0 = blockIdx.x * 128;
    const int b  = p0 / (MM * KK);
    const int ro = t >> 1, colbase = (t & 1) * 16;
    const int l = t & 31, warp = t >> 5;
    const int wo = warp >> 2, wp = warp & 3;

    // stage gather metadata + xyz diffs + xyz weight columns
    if (t < 128) {
        int p = p0 + t;
        int n = g_idx[p];
        s_n[t] = n;
        int q = p / KK;
        const float* px = xyz + ((size_t)b * NN + n) * 3;
        s_xyzd[0][t] = px[0] - g_newxyz[q*3+0];
        s_xyzd[1][t] = px[1] - g_newxyz[q*3+1];
        s_xyzd[2][t] = px[2] - g_newxyz[q*3+2];
        s_wxyz[0][t] = W[t*C1 + 0];
        s_wxyz[1][t] = W[t*C1 + 1];
        s_wxyz[2][t] = W[t*C1 + 2];
    }
    __syncthreads();

    const uint32_t uAh = smem_u32(sAh), uAl = smem_u32(sAl);
    const uint32_t uBh = smem_u32(sBh), uBl = smem_u32(sBl);
    const uint32_t aoffs = (uint32_t)((wo*64 + (l & 15)) * (RS*2) + (l >> 4) * 16);
    const uint32_t boffs = (uint32_t)((wp*32 + ((l >> 4) & 1)*8 + (l & 7)) * (RS*2)
                                      + ((l >> 3) & 1) * 16);

    const int nro = s_n[ro];
    const float* frow = g_featT + ((size_t)b * NN + nro) * CC;

    float wreg[16], areg[16];
    {
        #pragma unroll
        for (int e = 0; e < 16; e++)
            wreg[e] = W[ro*C1 + 3 + colbase + e];        // feat-channel weights
        #pragma unroll
        for (int i = 0; i < 4; i++)
            *(float4*)&areg[i*4] = *(const float4*)&frow[colbase + i*4];
    }

    float acc[4][4][4];
    #pragma unroll
    for (int mi = 0; mi < 4; mi++)
        #pragma unroll
        for (int nf = 0; nf < 4; nf++)
            #pragma unroll
            for (int j = 0; j < 4; j++) acc[mi][nf][j] = 0.f;

    for (int ch = 0; ch < 4; ch++) {
        #pragma unroll
        for (int i = 0; i < 8; i++) {
            int e = i * 2;
            int off = ro * RS + colbase + e;
            split2_store(wreg[e], wreg[e+1], &sAh[off], &sAl[off]);
            split2_store(areg[e], areg[e+1], &sBh[off], &sBl[off]);
        }
        __syncthreads();
        if (ch < 3) {
            int c0 = (ch + 1) * 32;
            #pragma unroll
            for (int e = 0; e < 16; e++)
                wreg[e] = W[ro*C1 + 3 + c0 + colbase + e];
            #pragma unroll
            for (int i = 0; i < 4; i++)
                *(float4*)&areg[i*4] = *(const float4*)&frow[c0 + colbase + i*4];
        }
        #pragma unroll
        for (int ks = 0; ks < 2; ks++) {
            uint32_t ah[4][4], al[4][4];
            #pragma unroll
            for (int mi = 0; mi < 4; mi++) {
                uint32_t d = aoffs + mi * 16 * (RS*2) + ks * 32;
                ldsm4(ah[mi], uAh + d);
                ldsm4(al[mi], uAl + d);
            }
            uint32_t bh[4][2], bl[4][2];
            #pragma unroll
            for (int g = 0; g < 2; g++) {
                uint32_t d = boffs + g * 16 * (RS*2) + ks * 32;
                uint32_t r4[4];
                ldsm4(r4, uBh + d);
                bh[g*2][0] = r4[0]; bh[g*2][1] = r4[1];
                bh[g*2+1][0] = r4[2]; bh[g*2+1][1] = r4[3];
                ldsm4(r4, uBl + d);
                bl[g*2][0] = r4[0]; bl[g*2][1] = r4[1];
                bl[g*2+1][0] = r4[2]; bl[g*2+1][1] = r4[3];
            }
            #pragma unroll
            for (int mi = 0; mi < 4; mi++)
                #pragma unroll
                for (int nf = 0; nf < 4; nf++) {
                    mma16816(acc[mi][nf], ah[mi], bh[nf]);
                    mma16816(acc[mi][nf], ah[mi], bl[nf]);
                    mma16816(acc[mi][nf], al[mi], bh[nf]);
                }
        }
        __syncthreads();
    }

    // ---- exact fp32 rank-3 xyz update into mma accumulators ----
    const int r = l >> 2, q = l & 3;
    {
        float wxa[4][3], wxb[4][3];
        #pragma unroll
        for (int mi = 0; mi < 4; mi++) {
            int o_a = wo*64 + mi*16 + r;
            #pragma unroll
            for (int c = 0; c < 3; c++) {
                wxa[mi][c] = s_wxyz[c][o_a];
                wxb[mi][c] = s_wxyz[c][o_a + 8];
            }
        }
        #pragma unroll
        for (int nf = 0; nf < 4; nf++) {
            int p_loc = wp*32 + nf*8 + q*2;
            float xd0[3], xd1[3];
            #pragma unroll
            for (int c = 0; c < 3; c++) {
                xd0[c] = s_xyzd[c][p_loc];
                xd1[c] = s_xyzd[c][p_loc + 1];
            }
            #pragma unroll
            for (int mi = 0; mi < 4; mi++) {
                #pragma unroll
                for (int c = 0; c < 3; c++) {
                    acc[mi][nf][0] = fmaf(wxa[mi][c], xd0[c], acc[mi][nf][0]);
                    acc[mi][nf][1] = fmaf(wxa[mi][c], xd1[c], acc[mi][nf][1]);
                    acc[mi][nf][2] = fmaf(wxb[mi][c], xd0[c], acc[mi][nf][2]);
                    acc[mi][nf][3] = fmaf(wxb[mi][c], xd1[c], acc[mi][nf][3]);
                }
            }
        }
    }

    // ---- epilogue: bias, store y1 channel-major, BN partials ----
    const int tile4 = blockIdx.x * 4 + wp;
    #pragma unroll
    for (int mi = 0; mi < 4; mi++) {
        int o_a = wo*64 + mi*16 + r;
        int o_b = o_a + 8;
        float bsa = bias[o_a], bsb = bias[o_b];
        float sa = 0.f, sa2 = 0.f, sb = 0.f, sb2 = 0.f;
        #pragma unroll
        for (int nf = 0; nf < 4; nf++) {
            float v0 = acc[mi][nf][0] + bsa;
            float v1 = acc[mi][nf][1] + bsa;
            float v2 = acc[mi][nf][2] + bsb;
            float v3 = acc[mi][nf][3] + bsb;
            int p = p0 + wp*32 + nf*8 + q*2;
            *(float2*)&g_y1[(size_t)o_a * PP + p] = make_float2(v0, v1);
            *(float2*)&g_y1[(size_t)o_b * PP + p] = make_float2(v2, v3);
            sa += v0 + v1; sa2 += v0*v0 + v1*v1;
            sb += v2 + v3; sb2 += v2*v2 + v3*v3;
        }
        #pragma unroll
        for (int d = 1; d < 4; d <<= 1) {
            sa  += __shfl_xor_sync(0xffffffffu, sa,  d);
            sa2 += __shfl_xor_sync(0xffffffffu, sa2, d);
            sb  += __shfl_xor_sync(0xffffffffu, sb,  d);
            sb2 += __shfl_xor_sync(0xffffffffu, sb2, d);
        }
        if (q == 0) {
            g_part1[(size_t)o_a * NT4 + tile4] = make_float2(sa, sa2);
            g_part1[(size_t)o_b * NT4 + tile4] = make_float2(sb, sb2);
        }
    }
}

// ---------------------------------------------------------------------------
// bf16 3-pass mma.sync GEMM (layers 2 and 3)
// ---------------------------------------------------------------------------
template<bool LAST>
__global__ __launch_bounds__(256, 1) void k_gemm_mma(
    const float* __restrict__ yin, const float2* __restrict__ ab,
    const float* __restrict__ W, const float* __restrict__ bias,
    float* __restrict__ yout, float2* __restrict__ part)
{
    __shared__ __nv_bfloat16 sAh[128*RS];
    __shared__ __nv_bfloat16 sAl[128*RS];
    __shared__ __nv_bfloat16 sBh[128*RS];
    __shared__ __nv_bfloat16 sBl[128*RS];

    const int t    = threadIdx.x;
    const int p0   = blockIdx.x * 128;
    const int oOff = blockIdx.y * 128;
    const int ro = t >> 1, colbase = (t & 1) * 16;
    const int l = t & 31, warp = t >> 5;
    const int wo = warp >> 2, wp = warp & 3;

    const uint32_t uAh = smem_u32(sAh), uAl = smem_u32(sAl);
    const uint32_t uBh = smem_u32(sBh), uBl = smem_u32(sBl);
    const uint32_t aoffs = (uint32_t)((wo*64 + (l & 15)) * (RS*2) + (l >> 4) * 16);
    const uint32_t boffs = (uint32_t)((wp*32 + ((l >> 4) & 1)*8 + (l & 7)) * (RS*2)
                                      + ((l >> 3) & 1) * 16);

    float wreg[16], areg[16];
    {
        #pragma unroll
        for (int i = 0; i < 4; i++)
            *(float4*)&wreg[i*4] = *(const float4*)&W[(size_t)(oOff+ro)*CC + colbase + i*4];
        #pragma unroll
        for (int e = 0; e < 16; e++) {
            int c = colbase + e;
            float2 s = ab[c];
            float v = yin[(size_t)c * PP + p0 + ro];
            areg[e] = fmaxf(fmaf(v, s.x, s.y), 0.f);
        }
    }

    float acc[4][4][4];
    #pragma unroll
    for (int mi = 0; mi < 4; mi++)
        #pragma unroll
        for (int nf = 0; nf < 4; nf++)
            #pragma unroll
            for (int j = 0; j < 4; j++) acc[mi][nf][j] = 0.f;

    for (int ch = 0; ch < 4; ch++) {
        #pragma unroll
        for (int i = 0; i < 8; i++) {
            int e = i * 2;
            int off = ro * RS + colbase + e;
            split2_store(wreg[e], wreg[e+1], &sAh[off], &sAl[off]);
            split2_store(areg[e], areg[e+1], &sBh[off], &sBl[off]);
        }
        __syncthreads();
        if (ch < 3) {
            int c0 = (ch + 1) * 32;
            #pragma unroll
            for (int i = 0; i < 4; i++)
                *(float4*)&wreg[i*4] =
                    *(const float4*)&W[(size_t)(oOff+ro)*CC + c0 + colbase + i*4];
            #pragma unroll
            for (int e = 0; e < 16; e++) {
                int c = c0 + colbase + e;
                float2 s = ab[c];
                float v = yin[(size_t)c * PP + p0 + ro];
                areg[e] = fmaxf(fmaf(v, s.x, s.y), 0.f);
            }
        }
        #pragma unroll
        for (int ks = 0; ks < 2; ks++) {
            uint32_t ah[4][4], al[4][4];
            #pragma unroll
            for (int mi = 0; mi < 4; mi++) {
                uint32_t d = aoffs + mi * 16 * (RS*2) + ks * 32;
                ldsm4(ah[mi], uAh + d);
                ldsm4(al[mi], uAl + d);
            }
            uint32_t bh[4][2], bl[4][2];
            #pragma unroll
            for (int g = 0; g < 2; g++) {
                uint32_t d = boffs + g * 16 * (RS*2) + ks * 32;
                uint32_t r4[4];
                ldsm4(r4, uBh + d);
                bh[g*2][0] = r4[0]; bh[g*2][1] = r4[1];
                bh[g*2+1][0] = r4[2]; bh[g*2+1][1] = r4[3];
                ldsm4(r4, uBl + d);
                bl[g*2][0] = r4[0]; bl[g*2][1] = r4[1];
                bl[g*2+1][0] = r4[2]; bl[g*2+1][1] = r4[3];
            }
            #pragma unroll
            for (int mi = 0; mi < 4; mi++)
                #pragma unroll
                for (int nf = 0; nf < 4; nf++) {
                    mma16816(acc[mi][nf], ah[mi], bh[nf]);
                    mma16816(acc[mi][nf], ah[mi], bl[nf]);
                    mma16816(acc[mi][nf], al[mi], bh[nf]);
                }
        }
        __syncthreads();
    }

    const int r = l >> 2, q = l & 3;
    const int tile4 = blockIdx.x * 4 + wp;
    #pragma unroll
    for (int mi = 0; mi < 4; mi++) {
        int o_a = oOff + wo*64 + mi*16 + r;
        int o_b = o_a + 8;
        float bsa = bias[o_a], bsb = bias[o_b];
        float sa = 0.f, sa2 = 0.f, sb = 0.f, sb2 = 0.f;
        float mxa = -INFINITY, mna = INFINITY, mxb = -INFINITY, mnb = INFINITY;
        #pragma unroll
        for (int nf = 0; nf < 4; nf++) {
            float v0 = acc[mi][nf][0] + bsa;
            float v1 = acc[mi][nf][1] + bsa;
            float v2 = acc[mi][nf][2] + bsb;
            float v3 = acc[mi][nf][3] + bsb;
            int p = p0 + wp*32 + nf*8 + q*2;
            if (!LAST) {
                *(float2*)&yout[(size_t)o_a * PP + p] = make_float2(v0, v1);
                *(float2*)&yout[(size_t)o_b * PP + p] = make_float2(v2, v3);
            }
            sa += v0 + v1; sa2 += v0*v0 + v1*v1;
            sb += v2 + v3; sb2 += v2*v2 + v3*v3;
            if (LAST) {
                mxa = fmaxf(mxa, fmaxf(v0, v1)); mna = fminf(mna, fminf(v0, v1));
                mxb = fmaxf(mxb, fmaxf(v2, v3)); mnb = fminf(mnb, fminf(v2, v3));
            }
        }
        #pragma unroll
        for (int d = 1; d < 4; d <<= 1) {
            sa  += __shfl_xor_sync(0xffffffffu, sa,  d);
            sa2 += __shfl_xor_sync(0xffffffffu, sa2, d);
            sb  += __shfl_xor_sync(0xffffffffu, sb,  d);
            sb2 += __shfl_xor_sync(0xffffffffu, sb2, d);
            if (LAST) {
                mxa = fmaxf(mxa, __shfl_xor_sync(0xffffffffu, mxa, d));
                mna = fminf(mna, __shfl_xor_sync(0xffffffffu, mna, d));
                mxb = fmaxf(mxb, __shfl_xor_sync(0xffffffffu, mxb, d));
                mnb = fminf(mnb, __shfl_xor_sync(0xffffffffu, mnb, d));
            }
        }
        if (q == 0) {
            part[(size_t)o_a * NT4 + tile4] = make_float2(sa, sa2);
            part[(size_t)o_b * NT4 + tile4] = make_float2(sb, sb2);
            if (LAST) {
                int gm = blockIdx.x * 4 + wp;
                g_mx[(size_t)gm * O3 + o_a] = mxa;
                g_mn[(size_t)gm * O3 + o_a] = mna;
                g_mx[(size_t)gm * O3 + o_b] = mxb;
                g_mn[(size_t)gm * O3 + o_b] = mnb;
            }
        }
    }
}

// ---------------------------------------------------------------------------
// Finalize: relu(a*ext + b), ext = max/min by sign(a)
// ---------------------------------------------------------------------------
__global__ void k_finalize(float* __restrict__ out) {
    __shared__ float tile[32][33];
    int gm0 = blockIdx.x * 32;
    int o0  = blockIdx.y * 32;
    int tx = threadIdx.x, ty = threadIdx.y;
    #pragma unroll
    for (int j = 0; j < 32; j += 8) {
        int gm = gm0 + ty + j;
        int o  = o0 + tx;
        float2 s = g_ab3[o];
        float ext = (s.x >= 0.f) ? g_mx[(size_t)gm * O3 + o]
                                 : g_mn[(size_t)gm * O3 + o];
        tile[tx][ty + j] = fmaxf(fmaf(ext, s.x, s.y), 0.f);
    }
    __syncthreads();
    int b = gm0 / MM;
    int m0 = gm0 - b * MM;
    #pragma unroll
    for (int j = 0; j < 32; j += 8) {
        int o = o0 + ty + j;
        out[(size_t)BB*MM*3 + ((size_t)(b * O3 + o)) * MM + m0 + tx] = tile[ty + j][tx];
    }
}

// ---------------------------------------------------------------------------
extern "C" void kernel_launch(void* const* d_in, const int* in_sizes, int n_in,
                              void* d_out, int out_size) {
    const float* xyz     = (const float*)d_in[0];
    const float* feat    = (const float*)d_in[1];
    const int*   indices = (const int*)d_in[2];
    const float* w1 = (const float*)d_in[3];
    const float* b1 = (const float*)d_in[4];
    const float* g1 = (const float*)d_in[5];
    const float* be1 = (const float*)d_in[6];
    const float* w2 = (const float*)d_in[7];
    const float* b2 = (const float*)d_in[8];
    const float* g2 = (const float*)d_in[9];
    const float* be2 = (const float*)d_in[10];
    const float* w3 = (const float*)d_in[11];
    const float* b3 = (const float*)d_in[12];
    const float* g3 = (const float*)d_in[13];
    const float* be3 = (const float*)d_in[14];
    float* out = (float*)d_out;

    float* y1; cudaGetSymbolAddress((void**)&y1, g_y1);
    float* y2; cudaGetSymbolAddress((void**)&y2, g_y2);
    float2* ab1; cudaGetSymbolAddress((void**)&ab1, g_ab1);
    float2* ab2; cudaGetSymbolAddress((void**)&ab2, g_ab2);
    float2* ab3; cudaGetSymbolAddress((void**)&ab3, g_ab3);
    float2* part1; cudaGetSymbolAddress((void**)&part1, g_part1);
    float2* part2; cudaGetSymbolAddress((void**)&part2, g_part2);
    float2* part3; cudaGetSymbolAddress((void**)&part3, g_part3);

    k_gather_newxyz<<<(BB*MM + 255) / 256, 256>>>(xyz, indices, out);
    k_ballquery<<<BB*MM, 512>>>(xyz);
    k_transpose_feat<<<dim3(NN/32, CC/32, BB), dim3(32, 8)>>>(feat);
    k_gemm1_mma<<<PP/128, 256>>>(xyz, w1, b1);
    k_bnfinal<<<O1, 256>>>(part1, NT4, g1, be1, ab1);
    k_gemm_mma<false><<<dim3(PP/128, 1), 256>>>(y1, ab1, w2, b2, y2, part2);
    k_bnfinal<<<O2, 256>>>(part2, NT4, g2, be2, ab2);
    k_gemm_mma<true><<<dim3(PP/128, 2), 256>>>(y2, ab2, w3, b3, nullptr, part3);
    k_bnfinal<<<O3, 256>>>(part3, NT4, g3, be3, ab3);
    k_finalize<<<dim3(BB*MM/32, O3/32), dim3(32, 8)>>>(out);
}

// round 7
// speedup vs baseline: 2.8467x; 1.2951x over previous
#include <cuda_runtime.h>
#include <cuda_bf16.h>
#include <cstdint>
#include <math.h>

// Problem constants
#define BB 4
#define NN 16384
#define CC 128
#define MM 1024
#define KK 32
#define PP (BB*MM*KK)     // 131072 points
#define C1 131
#define O1 128
#define O2 128
#define O3 256
#define RAD2 0.16f
#define EPSV 1e-5f
#define NT4 (PP/32)       // 4096 per-warp partial slots

// ---------------------------------------------------------------------------
// Scratch
// ---------------------------------------------------------------------------
__device__ float  g_featT[(size_t)BB*NN*CC];
__device__ float  g_newxyz[BB*MM*3];
__device__ int    g_idx[BB*MM*KK];
__device__ float  g_y1[(size_t)O1*PP];
__device__ float  g_y2[(size_t)O2*PP];
__device__ float2 g_ab1[O1];
__device__ float2 g_ab2[O2];
__device__ float2 g_ab3[O3];
__device__ float2 g_part1[(size_t)O1*NT4];
__device__ float2 g_part2[(size_t)O2*NT4];
__device__ float2 g_part3[(size_t)O3*NT4];
__device__ float  g_mx[(size_t)BB*MM*O3];
__device__ float  g_mn[(size_t)BB*MM*O3];

__device__ __forceinline__ uint32_t smem_u32(const void* p) {
    uint32_t a;
    asm("{ .reg .u64 tmp; cvta.to.shared.u64 tmp, %1; cvt.u32.u64 %0, tmp; }"
        : "=r"(a) : "l"(p));
    return a;
}

// ---------------------------------------------------------------------------
// K0: gather new_xyz
// ---------------------------------------------------------------------------
__global__ void k_gather_newxyz(const float* __restrict__ xyz,
                                const int* __restrict__ indices,
                                float* __restrict__ out) {
    int i = blockIdx.x * blockDim.x + threadIdx.x;
    if (i >= BB * MM) return;
    int b = i / MM;
    int n = indices[i];
    const float* src = xyz + ((size_t)b * NN + n) * 3;
    float x = src[0], y = src[1], z = src[2];
    g_newxyz[i*3+0] = x; g_newxyz[i*3+1] = y; g_newxyz[i*3+2] = z;
    out[i*3+0] = x; out[i*3+1] = y; out[i*3+2] = z;
}

// ---------------------------------------------------------------------------
// K1: transpose features (B,C,N) -> (B,N,C)
// ---------------------------------------------------------------------------
__global__ void k_transpose_feat(const float* __restrict__ f) {
    __shared__ float t[32][33];
    int b  = blockIdx.z;
    int c0 = blockIdx.y * 32;
    int n0 = blockIdx.x * 32;
    int tx = threadIdx.x, ty = threadIdx.y;
    #pragma unroll
    for (int j = 0; j < 32; j += 8)
        t[ty + j][tx] = f[((size_t)b * CC + c0 + ty + j) * NN + n0 + tx];
    __syncthreads();
    #pragma unroll
    for (int j = 0; j < 32; j += 8)
        g_featT[((size_t)b * NN + n0 + ty + j) * CC + c0 + tx] = t[tx][ty + j];
}

// ---------------------------------------------------------------------------
// K2: ball query — BLOCK per query, 512 threads, 1024 candidates/iteration
// (2 consecutive candidates per thread; index order preserved).
// ---------------------------------------------------------------------------
__global__ __launch_bounds__(512) void k_ballquery(const float* __restrict__ xyz) {
    __shared__ int s_found[KK];
    __shared__ int s_wcnt[2][16];
    const int q = blockIdx.x;
    const int b = q / MM;
    const int t = threadIdx.x, l = t & 31, w = t >> 5;
    const float qx = g_newxyz[q*3+0], qy = g_newxyz[q*3+1], qz = g_newxyz[q*3+2];
    const float* base = xyz + (size_t)b * NN * 3;
    const unsigned ltmask = (1u << l) - 1u;
    int cnt = 0;
    int parity = 0;
    for (int n0 = 0; n0 < NN; n0 += 1024, parity ^= 1) {
        int n = n0 + t * 2;
        float2 u0 = *(const float2*)&base[(size_t)n*3];
        float2 u1 = *(const float2*)&base[(size_t)n*3 + 2];
        float2 u2 = *(const float2*)&base[(size_t)n*3 + 4];
        float dxa = u0.x - qx, dya = u0.y - qy, dza = u1.x - qz;
        float dxb = u1.y - qx, dyb = u2.x - qy, dzb = u2.y - qz;
        bool wa = (dxa*dxa + dya*dya + dza*dza) < RAD2;
        bool wb = (dxb*dxb + dyb*dyb + dzb*dzb) < RAD2;
        unsigned ba = __ballot_sync(0xffffffffu, wa);
        unsigned bb = __ballot_sync(0xffffffffu, wb);
        if (l == 0) s_wcnt[parity][w] = __popc(ba) + __popc(bb);
        __syncthreads();
        int off = cnt, tot = 0;
        #pragma unroll
        for (int i = 0; i < 16; i++) {
            int c = s_wcnt[parity][i];
            if (i < w) off += c;
            tot += c;
        }
        if (wa | wb) {
            int ra = off + __popc(ba & ltmask) + __popc(bb & ltmask);
            if (wa && ra < KK) s_found[ra] = n;
            int rb = ra + (wa ? 1 : 0);
            if (wb && rb < KK) s_found[rb] = n + 1;
        }
        cnt += tot;
        if (cnt >= KK) break;
    }
    __syncthreads();
    if (t < KK) {
        int pad = (cnt > 0) ? s_found[0] : 0;
        g_idx[q * KK + t] = (t < cnt) ? s_found[t] : pad;
    }
}

// ---------------------------------------------------------------------------
// BN finalize
// ---------------------------------------------------------------------------
__global__ __launch_bounds__(256) void k_bnfinal(const float2* __restrict__ part,
                                                 int nparts,
                                                 const float* __restrict__ gamma,
                                                 const float* __restrict__ beta,
                                                 float2* __restrict__ abo) {
    __shared__ float2 red[256];
    int o = blockIdx.x, t = threadIdx.x;
    float s = 0.f, s2 = 0.f;
    for (int i = t; i < nparts; i += 256) {
        float2 v = part[(size_t)o * nparts + i];
        s += v.x; s2 += v.y;
    }
    red[t] = make_float2(s, s2);
    __syncthreads();
    for (int st = 128; st > 0; st >>= 1) {
        if (t < st) { red[t].x += red[t+st].x; red[t].y += red[t+st].y; }
        __syncthreads();
    }
    if (t == 0) {
        float mean = red[0].x / (float)PP;
        float var  = red[0].y / (float)PP - mean * mean;
        float a = gamma[o] * rsqrtf(var + EPSV);
        abo[o] = make_float2(a, beta[o] - a * mean);
    }
}

// ---------------------------------------------------------------------------
// mma helpers
// ---------------------------------------------------------------------------
#define RS 40   // smem row stride in bf16 elems

__device__ __forceinline__ void ldsm4(uint32_t* r, uint32_t addr) {
    asm volatile("ldmatrix.sync.aligned.m8n8.x4.shared.b16 {%0,%1,%2,%3}, [%4];"
                 : "=r"(r[0]), "=r"(r[1]), "=r"(r[2]), "=r"(r[3]) : "r"(addr));
}
__device__ __forceinline__ void mma16816(float* d, const uint32_t* a, const uint32_t* b) {
    asm volatile(
        "mma.sync.aligned.m16n8k16.row.col.f32.bf16.bf16.f32 "
        "{%0,%1,%2,%3}, {%4,%5,%6,%7}, {%8,%9}, {%0,%1,%2,%3};"
        : "+f"(d[0]), "+f"(d[1]), "+f"(d[2]), "+f"(d[3])
        : "r"(a[0]), "r"(a[1]), "r"(a[2]), "r"(a[3]), "r"(b[0]), "r"(b[1]));
}
__device__ __forceinline__ void split2_store(float v0, float v1,
                                             __nv_bfloat16* hi, __nv_bfloat16* lo) {
    __nv_bfloat16 h0 = __float2bfloat16(v0);
    __nv_bfloat16 h1 = __float2bfloat16(v1);
    __nv_bfloat16 l0 = __float2bfloat16(v0 - __bfloat162float(h0));
    __nv_bfloat16 l1 = __float2bfloat16(v1 - __bfloat162float(h1));
    __nv_bfloat162 hh; hh.x = h0; hh.y = h1;
    __nv_bfloat162 ll; ll.x = l0; ll.y = l1;
    *(__nv_bfloat162*)hi = hh;
    *(__nv_bfloat162*)lo = ll;
}

// shared mma mainloop body: load frags for 2 k-steps of current chunk + mma
#define MMA_CHUNK_BODY() \
    _Pragma("unroll") \
    for (int ks = 0; ks < 2; ks++) { \
        uint32_t ah[4][4], al[4][4]; \
        _Pragma("unroll") \
        for (int mi = 0; mi < 4; mi++) { \
            uint32_t d = aoffs + mi * 16 * (RS*2) + ks * 32; \
            ldsm4(ah[mi], uAh + d); \
            ldsm4(al[mi], uAl + d); \
        } \
        uint32_t bh[4][2], bl[4][2]; \
        _Pragma("unroll") \
        for (int g = 0; g < 2; g++) { \
            uint32_t d = boffs + g * 16 * (RS*2) + ks * 32; \
            uint32_t r4[4]; \
            ldsm4(r4, uBh + d); \
            bh[g*2][0] = r4[0]; bh[g*2][1] = r4[1]; \
            bh[g*2+1][0] = r4[2]; bh[g*2+1][1] = r4[3]; \
            ldsm4(r4, uBl + d); \
            bl[g*2][0] = r4[0]; bl[g*2][1] = r4[1]; \
            bl[g*2+1][0] = r4[2]; bl[g*2+1][1] = r4[3]; \
        } \
        _Pragma("unroll") \
        for (int mi = 0; mi < 4; mi++) \
            _Pragma("unroll") \
            for (int nf = 0; nf < 4; nf++) { \
                mma16816(acc[mi][nf], ah[mi], bh[nf]); \
                mma16816(acc[mi][nf], ah[mi], bl[nf]); \
                mma16816(acc[mi][nf], al[mi], bh[nf]); \
            } \
    }

// ---------------------------------------------------------------------------
// GEMM1 via mma + exact fp32 rank-3 xyz update
// ---------------------------------------------------------------------------
__global__ __launch_bounds__(256, 2) void k_gemm1_mma(
    const float* __restrict__ xyz, const float* __restrict__ W,
    const float* __restrict__ bias)
{
    __shared__ __nv_bfloat16 sAh[128*RS];
    __shared__ __nv_bfloat16 sAl[128*RS];
    __shared__ __nv_bfloat16 sBh[128*RS];
    __shared__ __nv_bfloat16 sBl[128*RS];
    __shared__ int   s_n[128];
    __shared__ float s_xyzd[3][128];
    __shared__ float s_wxyz[3][128];

    const int t  = threadIdx.x;
    const int p0 = blockIdx.x * 128;
    const int b  = p0 / (MM * KK);
    const int ro = t >> 1, colbase = (t & 1) * 16;
    const int l = t & 31, warp = t >> 5;
    const int wo = warp >> 2, wp = warp & 3;

    if (t < 128) {
        int p = p0 + t;
        int n = g_idx[p];
        s_n[t] = n;
        int q = p / KK;
        const float* px = xyz + ((size_t)b * NN + n) * 3;
        s_xyzd[0][t] = px[0] - g_newxyz[q*3+0];
        s_xyzd[1][t] = px[1] - g_newxyz[q*3+1];
        s_xyzd[2][t] = px[2] - g_newxyz[q*3+2];
        s_wxyz[0][t] = W[t*C1 + 0];
        s_wxyz[1][t] = W[t*C1 + 1];
        s_wxyz[2][t] = W[t*C1 + 2];
    }
    __syncthreads();

    const uint32_t uAh = smem_u32(sAh), uAl = smem_u32(sAl);
    const uint32_t uBh = smem_u32(sBh), uBl = smem_u32(sBl);
    const uint32_t aoffs = (uint32_t)((wo*64 + (l & 15)) * (RS*2) + (l >> 4) * 16);
    const uint32_t boffs = (uint32_t)((wp*32 + ((l >> 4) & 1)*8 + (l & 7)) * (RS*2)
                                      + ((l >> 3) & 1) * 16);

    const int nro = s_n[ro];
    const float* frow = g_featT + ((size_t)b * NN + nro) * CC;

    float acc[4][4][4];
    #pragma unroll
    for (int mi = 0; mi < 4; mi++)
        #pragma unroll
        for (int nf = 0; nf < 4; nf++)
            #pragma unroll
            for (int j = 0; j < 4; j++) acc[mi][nf][j] = 0.f;

    for (int ch = 0; ch < 4; ch++) {
        const int c0 = ch * 32;
        {
            float wreg[16], areg[16];
            #pragma unroll
            for (int e = 0; e < 16; e++)
                wreg[e] = W[ro*C1 + 3 + c0 + colbase + e];
            #pragma unroll
            for (int i = 0; i < 4; i++)
                *(float4*)&areg[i*4] = *(const float4*)&frow[c0 + colbase + i*4];
            #pragma unroll
            for (int i = 0; i < 8; i++) {
                int e = i * 2;
                int off = ro * RS + colbase + e;
                split2_store(wreg[e], wreg[e+1], &sAh[off], &sAl[off]);
                split2_store(areg[e], areg[e+1], &sBh[off], &sBl[off]);
            }
        }
        __syncthreads();
        MMA_CHUNK_BODY();
        __syncthreads();
    }

    // exact fp32 rank-3 xyz update
    const int r = l >> 2, q = l & 3;
    {
        float wxa[4][3], wxb[4][3];
        #pragma unroll
        for (int mi = 0; mi < 4; mi++) {
            int o_a = wo*64 + mi*16 + r;
            #pragma unroll
            for (int c = 0; c < 3; c++) {
                wxa[mi][c] = s_wxyz[c][o_a];
                wxb[mi][c] = s_wxyz[c][o_a + 8];
            }
        }
        #pragma unroll
        for (int nf = 0; nf < 4; nf++) {
            int p_loc = wp*32 + nf*8 + q*2;
            float xd0[3], xd1[3];
            #pragma unroll
            for (int c = 0; c < 3; c++) {
                xd0[c] = s_xyzd[c][p_loc];
                xd1[c] = s_xyzd[c][p_loc + 1];
            }
            #pragma unroll
            for (int mi = 0; mi < 4; mi++) {
                #pragma unroll
                for (int c = 0; c < 3; c++) {
                    acc[mi][nf][0] = fmaf(wxa[mi][c], xd0[c], acc[mi][nf][0]);
                    acc[mi][nf][1] = fmaf(wxa[mi][c], xd1[c], acc[mi][nf][1]);
                    acc[mi][nf][2] = fmaf(wxb[mi][c], xd0[c], acc[mi][nf][2]);
                    acc[mi][nf][3] = fmaf(wxb[mi][c], xd1[c], acc[mi][nf][3]);
                }
            }
        }
    }

    // epilogue
    const int tile4 = blockIdx.x * 4 + wp;
    #pragma unroll
    for (int mi = 0; mi < 4; mi++) {
        int o_a = wo*64 + mi*16 + r;
        int o_b = o_a + 8;
        float bsa = bias[o_a], bsb = bias[o_b];
        float sa = 0.f, sa2 = 0.f, sb = 0.f, sb2 = 0.f;
        #pragma unroll
        for (int nf = 0; nf < 4; nf++) {
            float v0 = acc[mi][nf][0] + bsa;
            float v1 = acc[mi][nf][1] + bsa;
            float v2 = acc[mi][nf][2] + bsb;
            float v3 = acc[mi][nf][3] + bsb;
            int p = p0 + wp*32 + nf*8 + q*2;
            *(float2*)&g_y1[(size_t)o_a * PP + p] = make_float2(v0, v1);
            *(float2*)&g_y1[(size_t)o_b * PP + p] = make_float2(v2, v3);
            sa += v0 + v1; sa2 += v0*v0 + v1*v1;
            sb += v2 + v3; sb2 += v2*v2 + v3*v3;
        }
        #pragma unroll
        for (int d = 1; d < 4; d <<= 1) {
            sa  += __shfl_xor_sync(0xffffffffu, sa,  d);
            sa2 += __shfl_xor_sync(0xffffffffu, sa2, d);
            sb  += __shfl_xor_sync(0xffffffffu, sb,  d);
            sb2 += __shfl_xor_sync(0xffffffffu, sb2, d);
        }
        if (q == 0) {
            g_part1[(size_t)o_a * NT4 + tile4] = make_float2(sa, sa2);
            g_part1[(size_t)o_b * NT4 + tile4] = make_float2(sb, sb2);
        }
    }
}

// ---------------------------------------------------------------------------
// bf16 3-pass mma.sync GEMM (layers 2 and 3)
// ---------------------------------------------------------------------------
template<bool LAST>
__global__ __launch_bounds__(256, 2) void k_gemm_mma(
    const float* __restrict__ yin, const float2* __restrict__ ab,
    const float* __restrict__ W, const float* __restrict__ bias,
    float* __restrict__ yout, float2* __restrict__ part)
{
    __shared__ __nv_bfloat16 sAh[128*RS];
    __shared__ __nv_bfloat16 sAl[128*RS];
    __shared__ __nv_bfloat16 sBh[128*RS];
    __shared__ __nv_bfloat16 sBl[128*RS];

    const int t    = threadIdx.x;
    const int p0   = blockIdx.x * 128;
    const int oOff = blockIdx.y * 128;
    const int ro = t >> 1, colbase = (t & 1) * 16;
    const int l = t & 31, warp = t >> 5;
    const int wo = warp >> 2, wp = warp & 3;

    const uint32_t uAh = smem_u32(sAh), uAl = smem_u32(sAl);
    const uint32_t uBh = smem_u32(sBh), uBl = smem_u32(sBl);
    const uint32_t aoffs = (uint32_t)((wo*64 + (l & 15)) * (RS*2) + (l >> 4) * 16);
    const uint32_t boffs = (uint32_t)((wp*32 + ((l >> 4) & 1)*8 + (l & 7)) * (RS*2)
                                      + ((l >> 3) & 1) * 16);

    float acc[4][4][4];
    #pragma unroll
    for (int mi = 0; mi < 4; mi++)
        #pragma unroll
        for (int nf = 0; nf < 4; nf++)
            #pragma unroll
            for (int j = 0; j < 4; j++) acc[mi][nf][j] = 0.f;

    for (int ch = 0; ch < 4; ch++) {
        const int c0 = ch * 32;
        {
            float wreg[16], areg[16];
            #pragma unroll
            for (int i = 0; i < 4; i++)
                *(float4*)&wreg[i*4] =
                    *(const float4*)&W[(size_t)(oOff+ro)*CC + c0 + colbase + i*4];
            #pragma unroll
            for (int e = 0; e < 16; e++) {
                int c = c0 + colbase + e;
                float2 s = ab[c];
                float v = yin[(size_t)c * PP + p0 + ro];
                areg[e] = fmaxf(fmaf(v, s.x, s.y), 0.f);
            }
            #pragma unroll
            for (int i = 0; i < 8; i++) {
                int e = i * 2;
                int off = ro * RS + colbase + e;
                split2_store(wreg[e], wreg[e+1], &sAh[off], &sAl[off]);
                split2_store(areg[e], areg[e+1], &sBh[off], &sBl[off]);
            }
        }
        __syncthreads();
        MMA_CHUNK_BODY();
        __syncthreads();
    }

    const int r = l >> 2, q = l & 3;
    const int tile4 = blockIdx.x * 4 + wp;
    #pragma unroll
    for (int mi = 0; mi < 4; mi++) {
        int o_a = oOff + wo*64 + mi*16 + r;
        int o_b = o_a + 8;
        float bsa = bias[o_a], bsb = bias[o_b];
        float sa = 0.f, sa2 = 0.f, sb = 0.f, sb2 = 0.f;
        float mxa = -INFINITY, mna = INFINITY, mxb = -INFINITY, mnb = INFINITY;
        #pragma unroll
        for (int nf = 0; nf < 4; nf++) {
            float v0 = acc[mi][nf][0] + bsa;
            float v1 = acc[mi][nf][1] + bsa;
            float v2 = acc[mi][nf][2] + bsb;
            float v3 = acc[mi][nf][3] + bsb;
            int p = p0 + wp*32 + nf*8 + q*2;
            if (!LAST) {
                *(float2*)&yout[(size_t)o_a * PP + p] = make_float2(v0, v1);
                *(float2*)&yout[(size_t)o_b * PP + p] = make_float2(v2, v3);
            }
            sa += v0 + v1; sa2 += v0*v0 + v1*v1;
            sb += v2 + v3; sb2 += v2*v2 + v3*v3;
            if (LAST) {
                mxa = fmaxf(mxa, fmaxf(v0, v1)); mna = fminf(mna, fminf(v0, v1));
                mxb = fmaxf(mxb, fmaxf(v2, v3)); mnb = fminf(mnb, fminf(v2, v3));
            }
        }
        #pragma unroll
        for (int d = 1; d < 4; d <<= 1) {
            sa  += __shfl_xor_sync(0xffffffffu, sa,  d);
            sa2 += __shfl_xor_sync(0xffffffffu, sa2, d);
            sb  += __shfl_xor_sync(0xffffffffu, sb,  d);
            sb2 += __shfl_xor_sync(0xffffffffu, sb2, d);
            if (LAST) {
                mxa = fmaxf(mxa, __shfl_xor_sync(0xffffffffu, mxa, d));
                mna = fminf(mna, __shfl_xor_sync(0xffffffffu, mna, d));
                mxb = fmaxf(mxb, __shfl_xor_sync(0xffffffffu, mxb, d));
                mnb = fminf(mnb, __shfl_xor_sync(0xffffffffu, mnb, d));
            }
        }
        if (q == 0) {
            part[(size_t)o_a * NT4 + tile4] = make_float2(sa, sa2);
            part[(size_t)o_b * NT4 + tile4] = make_float2(sb, sb2);
            if (LAST) {
                int gm = blockIdx.x * 4 + wp;
                g_mx[(size_t)gm * O3 + o_a] = mxa;
                g_mn[(size_t)gm * O3 + o_a] = mna;
                g_mx[(size_t)gm * O3 + o_b] = mxb;
                g_mn[(size_t)gm * O3 + o_b] = mnb;
            }
        }
    }
}

// ---------------------------------------------------------------------------
// Finalize: relu(a*ext + b), ext = max/min by sign(a)
// ---------------------------------------------------------------------------
__global__ void k_finalize(float* __restrict__ out) {
    __shared__ float tile[32][33];
    int gm0 = blockIdx.x * 32;
    int o0  = blockIdx.y * 32;
    int tx = threadIdx.x, ty = threadIdx.y;
    #pragma unroll
    for (int j = 0; j < 32; j += 8) {
        int gm = gm0 + ty + j;
        int o  = o0 + tx;
        float2 s = g_ab3[o];
        float ext = (s.x >= 0.f) ? g_mx[(size_t)gm * O3 + o]
                                 : g_mn[(size_t)gm * O3 + o];
        tile[tx][ty + j] = fmaxf(fmaf(ext, s.x, s.y), 0.f);
    }
    __syncthreads();
    int b = gm0 / MM;
    int m0 = gm0 - b * MM;
    #pragma unroll
    for (int j = 0; j < 32; j += 8) {
        int o = o0 + ty + j;
        out[(size_t)BB*MM*3 + ((size_t)(b * O3 + o)) * MM + m0 + tx] = tile[ty + j][tx];
    }
}

// ---------------------------------------------------------------------------
extern "C" void kernel_launch(void* const* d_in, const int* in_sizes, int n_in,
                              void* d_out, int out_size) {
    const float* xyz     = (const float*)d_in[0];
    const float* feat    = (const float*)d_in[1];
    const int*   indices = (const int*)d_in[2];
    const float* w1 = (const float*)d_in[3];
    const float* b1 = (const float*)d_in[4];
    const float* g1 = (const float*)d_in[5];
    const float* be1 = (const float*)d_in[6];
    const float* w2 = (const float*)d_in[7];
    const float* b2 = (const float*)d_in[8];
    const float* g2 = (const float*)d_in[9];
    const float* be2 = (const float*)d_in[10];
    const float* w3 = (const float*)d_in[11];
    const float* b3 = (const float*)d_in[12];
    const float* g3 = (const float*)d_in[13];
    const float* be3 = (const float*)d_in[14];
    float* out = (float*)d_out;

    float* y1; cudaGetSymbolAddress((void**)&y1, g_y1);
    float* y2; cudaGetSymbolAddress((void**)&y2, g_y2);
    float2* ab1; cudaGetSymbolAddress((void**)&ab1, g_ab1);
    float2* ab2; cudaGetSymbolAddress((void**)&ab2, g_ab2);
    float2* ab3; cudaGetSymbolAddress((void**)&ab3, g_ab3);
    float2* part1; cudaGetSymbolAddress((void**)&part1, g_part1);
    float2* part2; cudaGetSymbolAddress((void**)&part2, g_part2);
    float2* part3; cudaGetSymbolAddress((void**)&part3, g_part3);

    k_gather_newxyz<<<(BB*MM + 255) / 256, 256>>>(xyz, indices, out);
    k_ballquery<<<BB*MM, 512>>>(xyz);
    k_transpose_feat<<<dim3(NN/32, CC/32, BB), dim3(32, 8)>>>(feat);
    k_gemm1_mma<<<PP/128, 256>>>(xyz, w1, b1);
    k_bnfinal<<<O1, 256>>>(part1, NT4, g1, be1, ab1);
    k_gemm_mma<false><<<dim3(PP/128, 1), 256>>>(y1, ab1, w2, b2, y2, part2);
    k_bnfinal<<<O2, 256>>>(part2, NT4, g2, be2, ab2);
    k_gemm_mma<true><<<dim3(PP/128, 2), 256>>>(y2, ab2, w3, b3, nullptr, part3);
    k_bnfinal<<<O3, 256>>>(part3, NT4, g3, be3, ab3);
    k_finalize<<<dim3(BB*MM/32, O3/32), dim3(32, 8)>>>(out);
}

// round 8
// speedup vs baseline: 3.1069x; 1.0914x over previous
#include <cuda_runtime.h>
#include <cuda_bf16.h>
#include <cstdint>
#include <math.h>

// Problem constants
#define BB 4
#define NN 16384
#define CC 128
#define MM 1024
#define KK 32
#define PP (BB*MM*KK)     // 131072 points
#define C1 131
#define O1 128
#define O2 128
#define O3 256
#define RAD2 0.16f
#define EPSV 1e-5f
#define NT4 (PP/32)       // 4096 per-warp partial slots

// ---------------------------------------------------------------------------
// Scratch
// ---------------------------------------------------------------------------
__device__ float  g_featT[(size_t)BB*NN*CC];
__device__ float  g_newxyz[BB*MM*3];
__device__ int    g_idx[BB*MM*KK];
__device__ float  g_y1[(size_t)O1*PP];
__device__ float  g_y2[(size_t)O2*PP];
__device__ float2 g_ab1[O1];
__device__ float2 g_ab2[O2];
__device__ float2 g_ab3[O3];
__device__ float2 g_part1[(size_t)O1*NT4];
__device__ float2 g_part2[(size_t)O2*NT4];
__device__ float2 g_part3[(size_t)O3*NT4];
__device__ float  g_mx[(size_t)BB*MM*O3];
__device__ float  g_mn[(size_t)BB*MM*O3];
// frag-ordered weights: per frag (16 o x 16 k): 32 lanes x (4 hi + 4 lo) uint32
__device__ uint32_t g_wf1[64*256];    // w1 feature part: 8 o-tiles x 8 k-tiles
__device__ uint32_t g_wf2[64*256];
__device__ uint32_t g_wf3[128*256];   // 16 o-tiles x 8 k-tiles

__device__ __forceinline__ uint32_t smem_u32(const void* p) {
    uint32_t a;
    asm("{ .reg .u64 tmp; cvta.to.shared.u64 tmp, %1; cvt.u32.u64 %0, tmp; }"
        : "=r"(a) : "l"(p));
    return a;
}

// ---------------------------------------------------------------------------
// K0: gather new_xyz
// ---------------------------------------------------------------------------
__global__ void k_gather_newxyz(const float* __restrict__ xyz,
                                const int* __restrict__ indices,
                                float* __restrict__ out) {
    int i = blockIdx.x * blockDim.x + threadIdx.x;
    if (i >= BB * MM) return;
    int b = i / MM;
    int n = indices[i];
    const float* src = xyz + ((size_t)b * NN + n) * 3;
    float x = src[0], y = src[1], z = src[2];
    g_newxyz[i*3+0] = x; g_newxyz[i*3+1] = y; g_newxyz[i*3+2] = z;
    out[i*3+0] = x; out[i*3+1] = y; out[i*3+2] = z;
}

// ---------------------------------------------------------------------------
// K1: transpose features (B,C,N) -> (B,N,C)
// ---------------------------------------------------------------------------
__global__ void k_transpose_feat(const float* __restrict__ f) {
    __shared__ float t[32][33];
    int b  = blockIdx.z;
    int c0 = blockIdx.y * 32;
    int n0 = blockIdx.x * 32;
    int tx = threadIdx.x, ty = threadIdx.y;
    #pragma unroll
    for (int j = 0; j < 32; j += 8)
        t[ty + j][tx] = f[((size_t)b * CC + c0 + ty + j) * NN + n0 + tx];
    __syncthreads();
    #pragma unroll
    for (int j = 0; j < 32; j += 8)
        g_featT[((size_t)b * NN + n0 + ty + j) * CC + c0 + tx] = t[tx][ty + j];
}

// ---------------------------------------------------------------------------
// K1c: build frag-ordered hi/lo weights.
// frag (rt, kidx): rows rt*16..+15, cols Coff + kidx*16..+15 of W (ldW stride).
// lane l, reg j: j0:(R+(l>>2), Kb+2(l&3)) j1:(+8 row) j2:(+8 col) j3:(both).
// layout: gwf[(fr*32 + l)*8 + j] hi, +4+j lo.
// ---------------------------------------------------------------------------
__global__ void k_wfrag(const float* __restrict__ W, uint32_t* __restrict__ gwf,
                        int nfrag, int Coff, int ldW) {
    int tid = blockIdx.x * 256 + threadIdx.x;
    if (tid >= nfrag * 32) return;
    int fr = tid >> 5, l = tid & 31;
    int rt = fr >> 3, kidx = fr & 7;
    int row = rt * 16 + (l >> 2);
    int col = Coff + kidx * 16 + 2 * (l & 3);
    uint32_t* dst = gwf + (size_t)tid * 8;
    #pragma unroll
    for (int j = 0; j < 4; j++) {
        int rr = row + (j & 1) * 8;
        int cc2 = col + (j >> 1) * 8;
        float e0 = W[(size_t)rr * ldW + cc2];
        float e1 = W[(size_t)rr * ldW + cc2 + 1];
        __nv_bfloat16 h0 = __float2bfloat16(e0);
        __nv_bfloat16 h1 = __float2bfloat16(e1);
        __nv_bfloat16 l0 = __float2bfloat16(e0 - __bfloat162float(h0));
        __nv_bfloat16 l1 = __float2bfloat16(e1 - __bfloat162float(h1));
        __nv_bfloat162 hh; hh.x = h0; hh.y = h1;
        __nv_bfloat162 ll; ll.x = l0; ll.y = l1;
        // reg order: j index mapping (0: base, 1: +8row, 2: +8col, 3: both)
        dst[j]     = *(uint32_t*)&hh;
        dst[4 + j] = *(uint32_t*)&ll;
    }
}

// ---------------------------------------------------------------------------
// K2: ball query — BLOCK per query, 512 threads, 1024 candidates/iteration
// ---------------------------------------------------------------------------
__global__ __launch_bounds__(512) void k_ballquery(const float* __restrict__ xyz) {
    __shared__ int s_found[KK];
    __shared__ int s_wcnt[2][16];
    const int q = blockIdx.x;
    const int b = q / MM;
    const int t = threadIdx.x, l = t & 31, w = t >> 5;
    const float qx = g_newxyz[q*3+0], qy = g_newxyz[q*3+1], qz = g_newxyz[q*3+2];
    const float* base = xyz + (size_t)b * NN * 3;
    const unsigned ltmask = (1u << l) - 1u;
    int cnt = 0;
    int parity = 0;
    for (int n0 = 0; n0 < NN; n0 += 1024, parity ^= 1) {
        int n = n0 + t * 2;
        float2 u0 = *(const float2*)&base[(size_t)n*3];
        float2 u1 = *(const float2*)&base[(size_t)n*3 + 2];
        float2 u2 = *(const float2*)&base[(size_t)n*3 + 4];
        float dxa = u0.x - qx, dya = u0.y - qy, dza = u1.x - qz;
        float dxb = u1.y - qx, dyb = u2.x - qy, dzb = u2.y - qz;
        bool wa = (dxa*dxa + dya*dya + dza*dza) < RAD2;
        bool wb = (dxb*dxb + dyb*dyb + dzb*dzb) < RAD2;
        unsigned ba = __ballot_sync(0xffffffffu, wa);
        unsigned bb = __ballot_sync(0xffffffffu, wb);
        if (l == 0) s_wcnt[parity][w] = __popc(ba) + __popc(bb);
        __syncthreads();
        int off = cnt, tot = 0;
        #pragma unroll
        for (int i = 0; i < 16; i++) {
            int c = s_wcnt[parity][i];
            if (i < w) off += c;
            tot += c;
        }
        if (wa | wb) {
            int ra = off + __popc(ba & ltmask) + __popc(bb & ltmask);
            if (wa && ra < KK) s_found[ra] = n;
            int rb = ra + (wa ? 1 : 0);
            if (wb && rb < KK) s_found[rb] = n + 1;
        }
        cnt += tot;
        if (cnt >= KK) break;
    }
    __syncthreads();
    if (t < KK) {
        int pad = (cnt > 0) ? s_found[0] : 0;
        g_idx[q * KK + t] = (t < cnt) ? s_found[t] : pad;
    }
}

// ---------------------------------------------------------------------------
// BN finalize
// ---------------------------------------------------------------------------
__global__ __launch_bounds__(256) void k_bnfinal(const float2* __restrict__ part,
                                                 int nparts,
                                                 const float* __restrict__ gamma,
                                                 const float* __restrict__ beta,
                                                 float2* __restrict__ abo) {
    __shared__ float2 red[256];
    int o = blockIdx.x, t = threadIdx.x;
    float s = 0.f, s2 = 0.f;
    for (int i = t; i < nparts; i += 256) {
        float2 v = part[(size_t)o * nparts + i];
        s += v.x; s2 += v.y;
    }
    red[t] = make_float2(s, s2);
    __syncthreads();
    for (int st = 128; st > 0; st >>= 1) {
        if (t < st) { red[t].x += red[t+st].x; red[t].y += red[t+st].y; }
        __syncthreads();
    }
    if (t == 0) {
        float mean = red[0].x / (float)PP;
        float var  = red[0].y / (float)PP - mean * mean;
        float a = gamma[o] * rsqrtf(var + EPSV);
        abo[o] = make_float2(a, beta[o] - a * mean);
    }
}

// ---------------------------------------------------------------------------
// mma helpers
// ---------------------------------------------------------------------------
#define RS 40   // smem row stride in bf16 elems

__device__ __forceinline__ void ldsm4(uint32_t* r, uint32_t addr) {
    asm volatile("ldmatrix.sync.aligned.m8n8.x4.shared.b16 {%0,%1,%2,%3}, [%4];"
                 : "=r"(r[0]), "=r"(r[1]), "=r"(r[2]), "=r"(r[3]) : "r"(addr));
}
__device__ __forceinline__ void mma16816(float* d, const uint32_t* a, const uint32_t* b) {
    asm volatile(
        "mma.sync.aligned.m16n8k16.row.col.f32.bf16.bf16.f32 "
        "{%0,%1,%2,%3}, {%4,%5,%6,%7}, {%8,%9}, {%0,%1,%2,%3};"
        : "+f"(d[0]), "+f"(d[1]), "+f"(d[2]), "+f"(d[3])
        : "r"(a[0]), "r"(a[1]), "r"(a[2]), "r"(a[3]), "r"(b[0]), "r"(b[1]));
}
__device__ __forceinline__ void split2_store(float v0, float v1,
                                             __nv_bfloat16* hi, __nv_bfloat16* lo) {
    __nv_bfloat16 h0 = __float2bfloat16(v0);
    __nv_bfloat16 h1 = __float2bfloat16(v1);
    __nv_bfloat16 l0 = __float2bfloat16(v0 - __bfloat162float(h0));
    __nv_bfloat16 l1 = __float2bfloat16(v1 - __bfloat162float(h1));
    __nv_bfloat162 hh; hh.x = h0; hh.y = h1;
    __nv_bfloat162 ll; ll.x = l0; ll.y = l1;
    *(__nv_bfloat162*)hi = hh;
    *(__nv_bfloat162*)lo = ll;
}

// mainloop body: A frags from frag-ordered gmem (L1/L2-hot), B frags via ldmatrix
#define MMA_CHUNK_BODY(GWF) \
    _Pragma("unroll") \
    for (int ks = 0; ks < 2; ks++) { \
        uint32_t ah[4][4], al[4][4]; \
        _Pragma("unroll") \
        for (int mi = 0; mi < 4; mi++) { \
            const uint32_t* wp8 = (GWF) + ((size_t)(((rtBase + mi) << 3) + (ch << 1) + ks) * 32 + l) * 8; \
            uint4 h4 = *(const uint4*)wp8; \
            uint4 l4 = *(const uint4*)(wp8 + 4); \
            ah[mi][0] = h4.x; ah[mi][1] = h4.y; ah[mi][2] = h4.z; ah[mi][3] = h4.w; \
            al[mi][0] = l4.x; al[mi][1] = l4.y; al[mi][2] = l4.z; al[mi][3] = l4.w; \
        } \
        uint32_t bh[4][2], bl[4][2]; \
        _Pragma("unroll") \
        for (int g = 0; g < 2; g++) { \
            uint32_t d = boffs + g * 16 * (RS*2) + ks * 32; \
            uint32_t r4[4]; \
            ldsm4(r4, uBh + d); \
            bh[g*2][0] = r4[0]; bh[g*2][1] = r4[1]; \
            bh[g*2+1][0] = r4[2]; bh[g*2+1][1] = r4[3]; \
            ldsm4(r4, uBl + d); \
            bl[g*2][0] = r4[0]; bl[g*2][1] = r4[1]; \
            bl[g*2+1][0] = r4[2]; bl[g*2+1][1] = r4[3]; \
        } \
        _Pragma("unroll") \
        for (int mi = 0; mi < 4; mi++) \
            _Pragma("unroll") \
            for (int nf = 0; nf < 4; nf++) { \
                mma16816(acc[mi][nf], ah[mi], bh[nf]); \
                mma16816(acc[mi][nf], ah[mi], bl[nf]); \
                mma16816(acc[mi][nf], al[mi], bh[nf]); \
            } \
    }

// ---------------------------------------------------------------------------
// GEMM1 via mma + exact fp32 rank-3 xyz update
// ---------------------------------------------------------------------------
__global__ __launch_bounds__(256, 2) void k_gemm1_mma(
    const float* __restrict__ xyz, const float* __restrict__ W,
    const float* __restrict__ bias)
{
    __shared__ __nv_bfloat16 sBh[128*RS];
    __shared__ __nv_bfloat16 sBl[128*RS];
    __shared__ int   s_n[128];
    __shared__ float s_xyzd[3][128];
    __shared__ float s_wxyz[3][128];

    const int t  = threadIdx.x;
    const int p0 = blockIdx.x * 128;
    const int b  = p0 / (MM * KK);
    const int ro = t >> 1, colbase = (t & 1) * 16;
    const int l = t & 31, warp = t >> 5;
    const int wo = warp >> 2, wp = warp & 3;
    const int rtBase = wo * 4;

    if (t < 128) {
        int p = p0 + t;
        int n = g_idx[p];
        s_n[t] = n;
        int q = p / KK;
        const float* px = xyz + ((size_t)b * NN + n) * 3;
        s_xyzd[0][t] = px[0] - g_newxyz[q*3+0];
        s_xyzd[1][t] = px[1] - g_newxyz[q*3+1];
        s_xyzd[2][t] = px[2] - g_newxyz[q*3+2];
        s_wxyz[0][t] = W[t*C1 + 0];
        s_wxyz[1][t] = W[t*C1 + 1];
        s_wxyz[2][t] = W[t*C1 + 2];
    }
    __syncthreads();

    const uint32_t uBh = smem_u32(sBh), uBl = smem_u32(sBl);
    const uint32_t boffs = (uint32_t)((wp*32 + ((l >> 4) & 1)*8 + (l & 7)) * (RS*2)
                                      + ((l >> 3) & 1) * 16);

    const int nro = s_n[ro];
    const float* frow = g_featT + ((size_t)b * NN + nro) * CC;

    float acc[4][4][4];
    #pragma unroll
    for (int mi = 0; mi < 4; mi++)
        #pragma unroll
        for (int nf = 0; nf < 4; nf++)
            #pragma unroll
            for (int j = 0; j < 4; j++) acc[mi][nf][j] = 0.f;

    for (int ch = 0; ch < 4; ch++) {
        const int c0 = ch * 32;
        {
            float areg[16];
            #pragma unroll
            for (int i = 0; i < 4; i++)
                *(float4*)&areg[i*4] = *(const float4*)&frow[c0 + colbase + i*4];
            #pragma unroll
            for (int i = 0; i < 8; i++) {
                int e = i * 2;
                int off = ro * RS + colbase + e;
                split2_store(areg[e], areg[e+1], &sBh[off], &sBl[off]);
            }
        }
        __syncthreads();
        MMA_CHUNK_BODY(g_wf1);
        __syncthreads();
    }

    // exact fp32 rank-3 xyz update
    const int r = l >> 2, q = l & 3;
    {
        float wxa[4][3], wxb[4][3];
        #pragma unroll
        for (int mi = 0; mi < 4; mi++) {
            int o_a = wo*64 + mi*16 + r;
            #pragma unroll
            for (int c = 0; c < 3; c++) {
                wxa[mi][c] = s_wxyz[c][o_a];
                wxb[mi][c] = s_wxyz[c][o_a + 8];
            }
        }
        #pragma unroll
        for (int nf = 0; nf < 4; nf++) {
            int p_loc = wp*32 + nf*8 + q*2;
            float xd0[3], xd1[3];
            #pragma unroll
            for (int c = 0; c < 3; c++) {
                xd0[c] = s_xyzd[c][p_loc];
                xd1[c] = s_xyzd[c][p_loc + 1];
            }
            #pragma unroll
            for (int mi = 0; mi < 4; mi++) {
                #pragma unroll
                for (int c = 0; c < 3; c++) {
                    acc[mi][nf][0] = fmaf(wxa[mi][c], xd0[c], acc[mi][nf][0]);
                    acc[mi][nf][1] = fmaf(wxa[mi][c], xd1[c], acc[mi][nf][1]);
                    acc[mi][nf][2] = fmaf(wxb[mi][c], xd0[c], acc[mi][nf][2]);
                    acc[mi][nf][3] = fmaf(wxb[mi][c], xd1[c], acc[mi][nf][3]);
                }
            }
        }
    }

    // epilogue
    const int tile4 = blockIdx.x * 4 + wp;
    #pragma unroll
    for (int mi = 0; mi < 4; mi++) {
        int o_a = wo*64 + mi*16 + r;
        int o_b = o_a + 8;
        float bsa = bias[o_a], bsb = bias[o_b];
        float sa = 0.f, sa2 = 0.f, sb = 0.f, sb2 = 0.f;
        #pragma unroll
        for (int nf = 0; nf < 4; nf++) {
            float v0 = acc[mi][nf][0] + bsa;
            float v1 = acc[mi][nf][1] + bsa;
            float v2 = acc[mi][nf][2] + bsb;
            float v3 = acc[mi][nf][3] + bsb;
            int p = p0 + wp*32 + nf*8 + q*2;
            *(float2*)&g_y1[(size_t)o_a * PP + p] = make_float2(v0, v1);
            *(float2*)&g_y1[(size_t)o_b * PP + p] = make_float2(v2, v3);
            sa += v0 + v1; sa2 += v0*v0 + v1*v1;
            sb += v2 + v3; sb2 += v2*v2 + v3*v3;
        }
        #pragma unroll
        for (int d = 1; d < 4; d <<= 1) {
            sa  += __shfl_xor_sync(0xffffffffu, sa,  d);
            sa2 += __shfl_xor_sync(0xffffffffu, sa2, d);
            sb  += __shfl_xor_sync(0xffffffffu, sb,  d);
            sb2 += __shfl_xor_sync(0xffffffffu, sb2, d);
        }
        if (q == 0) {
            g_part1[(size_t)o_a * NT4 + tile4] = make_float2(sa, sa2);
            g_part1[(size_t)o_b * NT4 + tile4] = make_float2(sb, sb2);
        }
    }
}

// ---------------------------------------------------------------------------
// bf16 3-pass mma.sync GEMM (layers 2 and 3)
// ---------------------------------------------------------------------------
template<bool LAST>
__global__ __launch_bounds__(256, 2) void k_gemm_mma(
    const float* __restrict__ yin, const float2* __restrict__ ab,
    const uint32_t* __restrict__ gwf, const float* __restrict__ bias,
    float* __restrict__ yout, float2* __restrict__ part)
{
    __shared__ __nv_bfloat16 sBh[128*RS];
    __shared__ __nv_bfloat16 sBl[128*RS];

    const int t    = threadIdx.x;
    const int p0   = blockIdx.x * 128;
    const int oOff = blockIdx.y * 128;
    const int ro = t >> 1, colbase = (t & 1) * 16;
    const int l = t & 31, warp = t >> 5;
    const int wo = warp >> 2, wp = warp & 3;
    const int rtBase = blockIdx.y * 8 + wo * 4;

    const uint32_t uBh = smem_u32(sBh), uBl = smem_u32(sBl);
    const uint32_t boffs = (uint32_t)((wp*32 + ((l >> 4) & 1)*8 + (l & 7)) * (RS*2)
                                      + ((l >> 3) & 1) * 16);

    float acc[4][4][4];
    #pragma unroll
    for (int mi = 0; mi < 4; mi++)
        #pragma unroll
        for (int nf = 0; nf < 4; nf++)
            #pragma unroll
            for (int j = 0; j < 4; j++) acc[mi][nf][j] = 0.f;

    for (int ch = 0; ch < 4; ch++) {
        const int c0 = ch * 32;
        {
            float areg[16];
            #pragma unroll
            for (int e = 0; e < 16; e++) {
                int c = c0 + colbase + e;
                float2 s = ab[c];
                float v = yin[(size_t)c * PP + p0 + ro];
                areg[e] = fmaxf(fmaf(v, s.x, s.y), 0.f);
            }
            #pragma unroll
            for (int i = 0; i < 8; i++) {
                int e = i * 2;
                int off = ro * RS + colbase + e;
                split2_store(areg[e], areg[e+1], &sBh[off], &sBl[off]);
            }
        }
        __syncthreads();
        MMA_CHUNK_BODY(gwf);
        __syncthreads();
    }

    const int r = l >> 2, q = l & 3;
    const int tile4 = blockIdx.x * 4 + wp;
    #pragma unroll
    for (int mi = 0; mi < 4; mi++) {
        int o_a = oOff + wo*64 + mi*16 + r;
        int o_b = o_a + 8;
        float bsa = bias[o_a], bsb = bias[o_b];
        float sa = 0.f, sa2 = 0.f, sb = 0.f, sb2 = 0.f;
        float mxa = -INFINITY, mna = INFINITY, mxb = -INFINITY, mnb = INFINITY;
        #pragma unroll
        for (int nf = 0; nf < 4; nf++) {
            float v0 = acc[mi][nf][0] + bsa;
            float v1 = acc[mi][nf][1] + bsa;
            float v2 = acc[mi][nf][2] + bsb;
            float v3 = acc[mi][nf][3] + bsb;
            int p = p0 + wp*32 + nf*8 + q*2;
            if (!LAST) {
                *(float2*)&yout[(size_t)o_a * PP + p] = make_float2(v0, v1);
                *(float2*)&yout[(size_t)o_b * PP + p] = make_float2(v2, v3);
            }
            sa += v0 + v1; sa2 += v0*v0 + v1*v1;
            sb += v2 + v3; sb2 += v2*v2 + v3*v3;
            if (LAST) {
                mxa = fmaxf(mxa, fmaxf(v0, v1)); mna = fminf(mna, fminf(v0, v1));
                mxb = fmaxf(mxb, fmaxf(v2, v3)); mnb = fminf(mnb, fminf(v2, v3));
            }
        }
        #pragma unroll
        for (int d = 1; d < 4; d <<= 1) {
            sa  += __shfl_xor_sync(0xffffffffu, sa,  d);
            sa2 += __shfl_xor_sync(0xffffffffu, sa2, d);
            sb  += __shfl_xor_sync(0xffffffffu, sb,  d);
            sb2 += __shfl_xor_sync(0xffffffffu, sb2, d);
            if (LAST) {
                mxa = fmaxf(mxa, __shfl_xor_sync(0xffffffffu, mxa, d));
                mna = fminf(mna, __shfl_xor_sync(0xffffffffu, mna, d));
                mxb = fmaxf(mxb, __shfl_xor_sync(0xffffffffu, mxb, d));
                mnb = fminf(mnb, __shfl_xor_sync(0xffffffffu, mnb, d));
            }
        }
        if (q == 0) {
            part[(size_t)o_a * NT4 + tile4] = make_float2(sa, sa2);
            part[(size_t)o_b * NT4 + tile4] = make_float2(sb, sb2);
            if (LAST) {
                int gm = blockIdx.x * 4 + wp;
                g_mx[(size_t)gm * O3 + o_a] = mxa;
                g_mn[(size_t)gm * O3 + o_a] = mna;
                g_mx[(size_t)gm * O3 + o_b] = mxb;
                g_mn[(size_t)gm * O3 + o_b] = mnb;
            }
        }
    }
}

// ---------------------------------------------------------------------------
// Finalize: relu(a*ext + b), ext = max/min by sign(a)
// ---------------------------------------------------------------------------
__global__ void k_finalize(float* __restrict__ out) {
    __shared__ float tile[32][33];
    int gm0 = blockIdx.x * 32;
    int o0  = blockIdx.y * 32;
    int tx = threadIdx.x, ty = threadIdx.y;
    #pragma unroll
    for (int j = 0; j < 32; j += 8) {
        int gm = gm0 + ty + j;
        int o  = o0 + tx;
        float2 s = g_ab3[o];
        float ext = (s.x >= 0.f) ? g_mx[(size_t)gm * O3 + o]
                                 : g_mn[(size_t)gm * O3 + o];
        tile[tx][ty + j] = fmaxf(fmaf(ext, s.x, s.y), 0.f);
    }
    __syncthreads();
    int b = gm0 / MM;
    int m0 = gm0 - b * MM;
    #pragma unroll
    for (int j = 0; j < 32; j += 8) {
        int o = o0 + ty + j;
        out[(size_t)BB*MM*3 + ((size_t)(b * O3 + o)) * MM + m0 + tx] = tile[ty + j][tx];
    }
}

// ---------------------------------------------------------------------------
extern "C" void kernel_launch(void* const* d_in, const int* in_sizes, int n_in,
                              void* d_out, int out_size) {
    const float* xyz     = (const float*)d_in[0];
    const float* feat    = (const float*)d_in[1];
    const int*   indices = (const int*)d_in[2];
    const float* w1 = (const float*)d_in[3];
    const float* b1 = (const float*)d_in[4];
    const float* g1 = (const float*)d_in[5];
    const float* be1 = (const float*)d_in[6];
    const float* w2 = (const float*)d_in[7];
    const float* b2 = (const float*)d_in[8];
    const float* g2 = (const float*)d_in[9];
    const float* be2 = (const float*)d_in[10];
    const float* w3 = (const float*)d_in[11];
    const float* b3 = (const float*)d_in[12];
    const float* g3 = (const float*)d_in[13];
    const float* be3 = (const float*)d_in[14];
    float* out = (float*)d_out;

    float* y1; cudaGetSymbolAddress((void**)&y1, g_y1);
    float* y2; cudaGetSymbolAddress((void**)&y2, g_y2);
    float2* ab1; cudaGetSymbolAddress((void**)&ab1, g_ab1);
    float2* ab2; cudaGetSymbolAddress((void**)&ab2, g_ab2);
    float2* ab3; cudaGetSymbolAddress((void**)&ab3, g_ab3);
    float2* part1; cudaGetSymbolAddress((void**)&part1, g_part1);
    float2* part2; cudaGetSymbolAddress((void**)&part2, g_part2);
    float2* part3; cudaGetSymbolAddress((void**)&part3, g_part3);
    uint32_t* wf1; cudaGetSymbolAddress((void**)&wf1, g_wf1);
    uint32_t* wf2; cudaGetSymbolAddress((void**)&wf2, g_wf2);
    uint32_t* wf3; cudaGetSymbolAddress((void**)&wf3, g_wf3);

    k_gather_newxyz<<<(BB*MM + 255) / 256, 256>>>(xyz, indices, out);
    k_ballquery<<<BB*MM, 512>>>(xyz);
    k_wfrag<<<(64*32 + 255)/256, 256>>>(w1, wf1, 64, 3, C1);
    k_wfrag<<<(64*32 + 255)/256, 256>>>(w2, wf2, 64, 0, CC);
    k_wfrag<<<(128*32 + 255)/256, 256>>>(w3, wf3, 128, 0, CC);
    k_transpose_feat<<<dim3(NN/32, CC/32, BB), dim3(32, 8)>>>(feat);
    k_gemm1_mma<<<PP/128, 256>>>(xyz, w1, b1);
    k_bnfinal<<<O1, 256>>>(part1, NT4, g1, be1, ab1);
    k_gemm_mma<false><<<dim3(PP/128, 1), 256>>>(y1, ab1, wf2, b2, y2, part2);
    k_bnfinal<<<O2, 256>>>(part2, NT4, g2, be2, ab2);
    k_gemm_mma<true><<<dim3(PP/128, 2), 256>>>(y2, ab2, wf3, b3, nullptr, part3);
    k_bnfinal<<<O3, 256>>>(part3, NT4, g3, be3, ab3);
    k_finalize<<<dim3(BB*MM/32, O3/32), dim3(32, 8)>>>(out);
}